// round 8
// baseline (speedup 1.0000x reference)
#include <cuda_runtime.h>
#include <cuda_bf16.h>
#include <cstdint>

#define Bsz 4
#define Sq  2048
#define Dm  1024
#define Hh  16
#define Dh  64
#define Tt  (Bsz * Sq)

// ---------------- scratch ----------------
__device__ __nv_bfloat16 g_xh[(size_t)Tt * Dm];
__device__ __nv_bfloat16 g_xl[(size_t)Tt * Dm];
__device__ __nv_bfloat16 g_wh[(size_t)3 * Dm * Dm];
__device__ __nv_bfloat16 g_wl[(size_t)3 * Dm * Dm];
__device__ __nv_bfloat16 g_oh[(size_t)Dm * Dm];
__device__ __nv_bfloat16 g_ol[(size_t)Dm * Dm];
__device__ __nv_bfloat16 g_qh[(size_t)Tt * Dm];
__device__ __nv_bfloat16 g_ql[(size_t)Tt * Dm];
__device__ __nv_bfloat16 g_kh[(size_t)Tt * Dm];
__device__ __nv_bfloat16 g_kl[(size_t)Tt * Dm];
__device__ __nv_bfloat16 g_vh[(size_t)Tt * Dm];
__device__ __nv_bfloat16 g_vl[(size_t)Tt * Dm];
__device__ __nv_bfloat16 g_zh[(size_t)Tt * Dm];
__device__ __nv_bfloat16 g_zl[(size_t)Tt * Dm];

// ---------------- helpers (arch-stable PTX only) ----------------
__device__ __forceinline__ uint32_t smem_u32(const void* p) {
    uint32_t a;
    asm("{ .reg .u64 t; cvta.to.shared.u64 t, %1; cvt.u32.u64 %0, t; }" : "=r"(a) : "l"(p));
    return a;
}
#define CP_ASYNC16(dst, src) \
    asm volatile("cp.async.cg.shared.global [%0], [%1], 16;" :: "r"(dst), "l"(src))
#define CP_COMMIT() asm volatile("cp.async.commit_group;" ::: "memory")
#define CP_WAIT1()  asm volatile("cp.async.wait_group 1;" ::: "memory")
#define CP_WAIT0()  asm volatile("cp.async.wait_group 0;" ::: "memory")

__device__ __forceinline__ void ldmat4(uint32_t r[4], uint32_t a) {
    asm volatile("ldmatrix.sync.aligned.m8n8.x4.shared.b16 {%0,%1,%2,%3}, [%4];"
                 : "=r"(r[0]), "=r"(r[1]), "=r"(r[2]), "=r"(r[3]) : "r"(a));
}
__device__ __forceinline__ void ldmat4t(uint32_t r[4], uint32_t a) {
    asm volatile("ldmatrix.sync.aligned.m8n8.x4.trans.shared.b16 {%0,%1,%2,%3}, [%4];"
                 : "=r"(r[0]), "=r"(r[1]), "=r"(r[2]), "=r"(r[3]) : "r"(a));
}
__device__ __forceinline__ void mma16816(float* c, const uint32_t* a,
                                         uint32_t b0, uint32_t b1) {
    asm volatile("mma.sync.aligned.m16n8k16.row.col.f32.bf16.bf16.f32 "
                 "{%0,%1,%2,%3}, {%4,%5,%6,%7}, {%8,%9}, {%0,%1,%2,%3};"
                 : "+f"(c[0]), "+f"(c[1]), "+f"(c[2]), "+f"(c[3])
                 : "r"(a[0]), "r"(a[1]), "r"(a[2]), "r"(a[3]), "r"(b0), "r"(b1));
}
#define CVT2(res, hi, lo) \
    asm("cvt.rn.bf16x2.f32 %0, %1, %2;" : "=r"(res) : "f"(hi), "f"(lo))

__device__ __forceinline__ float fexp(float x) {
    x = fmaxf(x, -80.f);
    float t = x * 1.44269504f;
    float fk = t + 12582912.f;
    int   i  = __float_as_int(fk) - 0x4B400000;
    float f  = t - (fk - 12582912.f);
    float p = 1.33978e-3f;
    p = fmaf(p, f, 9.67839e-3f);
    p = fmaf(p, f, 5.55041e-2f);
    p = fmaf(p, f, 2.40227e-1f);
    p = fmaf(p, f, 6.93147e-1f);
    p = fmaf(p, f, 1.0f);
    return __int_as_float(__float_as_int(p) + (i << 23));
}
__device__ __forceinline__ void pack_pair(uint32_t& hv, uint32_t& lv, float v0, float v1) {
    CVT2(hv, v1, v0);
    float f0 = __uint_as_float(hv << 16);
    float f1 = __uint_as_float(hv & 0xFFFF0000u);
    CVT2(lv, v1 - f1, v0 - f0);
}
__device__ __forceinline__ void split_store(__nv_bfloat16* H, __nv_bfloat16* L,
                                            size_t idx, float v0, float v1) {
    uint32_t hv, lv;
    pack_pair(hv, lv, v0, v1);
    *(uint32_t*)(H + idx) = hv;
    *(uint32_t*)(L + idx) = lv;
}

// ---------------- prep ----------------
__global__ void conv_split(const float* __restrict__ in, __nv_bfloat16* __restrict__ hi,
                           __nv_bfloat16* __restrict__ lo, int n4)
{
    int i = blockIdx.x * blockDim.x + threadIdx.x;
    if (i >= n4) return;
    float4 v = ((const float4*)in)[i];
    uint32_t h0, h1, l0, l1;
    pack_pair(h0, l0, v.x, v.y);
    pack_pair(h1, l1, v.z, v.w);
    ((uint32_t*)hi)[2 * i] = h0; ((uint32_t*)hi)[2 * i + 1] = h1;
    ((uint32_t*)lo)[2 * i] = l0; ((uint32_t*)lo)[2 * i + 1] = l1;
}
__global__ void conv_wqkv(const float* __restrict__ wq, const float* __restrict__ wk,
                          const float* __restrict__ wv)
{
    int id = blockIdx.x * 256 + threadIdx.x;
    if (id >= 3 * Dm * Dm) return;
    int n = id >> 10, d = id & 1023;
    int proj = n >> 10, nl = n & 1023, h = nl >> 6, e = nl & 63;
    const float* W = (proj == 0 ? wq : proj == 1 ? wk : wv);
    float v = W[((size_t)h * Dm + d) * Dh + e];
    __nv_bfloat16 hh = __float2bfloat16(v);
    g_wh[id] = hh;
    g_wl[id] = __float2bfloat16(v - __bfloat162float(hh));
}
__global__ void conv_wo(const float* __restrict__ wo)
{
    int id = blockIdx.x * 256 + threadIdx.x;
    if (id >= Dm * Dm) return;
    int n = id >> 10, k = id & 1023;
    float v = wo[(size_t)k * Dm + n];
    __nv_bfloat16 hh = __float2bfloat16(v);
    g_oh[id] = hh;
    g_ol[id] = __float2bfloat16(v - __bfloat162float(hh));
}

// ---- bf16x3 HMMA GEMM: CTA 128x256, warp tile 64x64, 3-stage pipeline ------
// Per ks per warp: 16 ldmatrix (8KB) feed 96 MMAs -> 48 FLOP/smem-byte.
#define STAGE_BYTES 49152              /* Ah 8K + Al 8K + Bh 16K + Bl 16K */
#define GEMM_SMEM  (3 * STAGE_BYTES)   /* 147456 */

__global__ __launch_bounds__(256) void hmma_gemm(
    const __nv_bfloat16* __restrict__ Ah, const __nv_bfloat16* __restrict__ Al,
    const __nv_bfloat16* __restrict__ Bh, const __nv_bfloat16* __restrict__ Bl,
    const float* __restrict__ b0, const float* __restrict__ b1,
    const float* __restrict__ b2, float* __restrict__ C, int mode)
{
    extern __shared__ char smc[];
    const uint32_t sb = smem_u32(smc);
    const int tid = threadIdx.x, wid = tid >> 5, lane = tid & 31;
    const int warp_m = wid >> 2, warp_n = wid & 3;
    const int g = lane >> 3, r = lane & 7;
    const int m0  = blockIdx.x * 128;
    const int n0g = blockIdx.y * 256;
    const int proj = n0g >> 10;
    const int nl   = n0g & 1023;
    const float* bias = (proj == 0 ? b0 : proj == 1 ? b1 : b2);

    const __nv_bfloat16* srcA[2];
    const __nv_bfloat16* srcB[2];
    srcA[0] = Ah + (size_t)m0  * Dm;
    srcA[1] = Al + (size_t)m0  * Dm;
    srcB[0] = Bh + (size_t)n0g * Dm;
    srcB[1] = Bl + (size_t)n0g * Dm;

    // A frag (mi, ks): base ((warp_m*8 + (g&1))*4 + (g>>1))*128 + r*16, + mi*1024 + ks*256
    const uint32_t aoff0 = (uint32_t)(((warp_m * 8 + (g & 1)) * 4 + (g >> 1)) * 128 + r * 16);
    // B frag pair (np, ks): base ((warp_n*8 + (g>>1))*4 + (g&1))*128 + r*16, + np*1024 + ks*256
    const uint32_t boff0 = (uint32_t)(((warp_n * 8 + (g >> 1)) * 4 + (g & 1)) * 128 + r * 16);

    auto fill = [&](int buf, int k0) {
        const uint32_t stb = sb + buf * STAGE_BYTES;
        #pragma unroll
        for (int arr = 0; arr < 2; arr++) {        // A: 128 rows
            uint32_t abase = stb + arr * 8192;
            const __nv_bfloat16* s = srcA[arr];
            #pragma unroll
            for (int i = 0; i < 2; i++) {
                int cid = tid + 256 * i;
                int row = cid >> 2, kc = (cid & 3) * 8;
                CP_ASYNC16(abase + (uint32_t)(((row >> 3) * 4 + (kc >> 3)) * 128
                           + (row & 7) * 16),
                           s + (size_t)row * Dm + k0 + kc);
            }
        }
        #pragma unroll
        for (int arr = 0; arr < 2; arr++) {        // B: 256 rows
            uint32_t bbase = stb + 16384 + arr * 16384;
            const __nv_bfloat16* s = srcB[arr];
            #pragma unroll
            for (int i = 0; i < 4; i++) {
                int cid = tid + 256 * i;
                int row = cid >> 2, kc = (cid & 3) * 8;
                CP_ASYNC16(bbase + (uint32_t)(((row >> 3) * 4 + (kc >> 3)) * 128
                           + (row & 7) * 16),
                           s + (size_t)row * Dm + k0 + kc);
            }
        }
    };

    float acc[4][8][4];
    #pragma unroll
    for (int mi = 0; mi < 4; mi++)
        #pragma unroll
        for (int nj = 0; nj < 8; nj++)
            #pragma unroll
            for (int c = 0; c < 4; c++) acc[mi][nj][c] = 0.f;

    fill(0, 0);  CP_COMMIT();
    fill(1, 32); CP_COMMIT();

    const int NIT = Dm / 32;
    int buf = 0;
    for (int it = 0; it < NIT; it++) {
        if (it == NIT - 1) { CP_WAIT0(); } else { CP_WAIT1(); }
        __syncthreads();
        if (it + 2 < NIT) {
            int nb = buf + 2; if (nb >= 3) nb -= 3;
            fill(nb, (it + 2) * 32);
            CP_COMMIT();
        }

        const uint32_t stb = sb + buf * STAGE_BYTES;
        const uint32_t bAh = stb, bAl = stb + 8192;
        const uint32_t bBh = stb + 16384, bBl = stb + 32768;

        #pragma unroll
        for (int ks = 0; ks < 2; ks++) {
            uint32_t ah[4][4], al[4][4];
            #pragma unroll
            for (int mi = 0; mi < 4; mi++) {
                ldmat4(ah[mi], bAh + aoff0 + mi * 1024 + ks * 256);
                ldmat4(al[mi], bAl + aoff0 + mi * 1024 + ks * 256);
            }
            #pragma unroll
            for (int np = 0; np < 4; np++) {
                uint32_t bh[4], bl[4];
                ldmat4(bh, bBh + boff0 + np * 1024 + ks * 256);
                ldmat4(bl, bBl + boff0 + np * 1024 + ks * 256);
                #pragma unroll
                for (int mi = 0; mi < 4; mi++) {
                    mma16816(acc[mi][2 * np],     ah[mi], bh[0], bh[1]);
                    mma16816(acc[mi][2 * np + 1], ah[mi], bh[2], bh[3]);
                    mma16816(acc[mi][2 * np],     ah[mi], bl[0], bl[1]);
                    mma16816(acc[mi][2 * np + 1], ah[mi], bl[2], bl[3]);
                    mma16816(acc[mi][2 * np],     al[mi], bh[0], bh[1]);
                    mma16816(acc[mi][2 * np + 1], al[mi], bh[2], bh[3]);
                }
            }
        }
        if (++buf >= 3) buf = 0;
    }

    // epilogue
    const int gq = lane >> 2, tq = lane & 3;
    if (mode == 0) {
        #pragma unroll
        for (int mi = 0; mi < 4; mi++) {
            const int row = m0 + warp_m * 64 + mi * 16 + gq;
            #pragma unroll
            for (int nj = 0; nj < 8; nj++) {
                const int col = nl + warp_n * 64 + nj * 8 + tq * 2;
                const float bv0 = bias[col], bv1 = bias[col + 1];
                *(float2*)(C + (size_t)row * Dm + col) =
                    make_float2(acc[mi][nj][0] + bv0, acc[mi][nj][1] + bv1);
                *(float2*)(C + (size_t)(row + 8) * Dm + col) =
                    make_float2(acc[mi][nj][2] + bv0, acc[mi][nj][3] + bv1);
            }
        }
    } else {
        __nv_bfloat16* H = (proj == 0 ? g_qh : proj == 1 ? g_kh : g_vh);
        __nv_bfloat16* L = (proj == 0 ? g_ql : proj == 1 ? g_kl : g_vl);
        const float sc = (proj == 0) ? 0.125f : 1.f;
        #pragma unroll
        for (int mi = 0; mi < 4; mi++) {
            const size_t row = (size_t)(m0 + warp_m * 64 + mi * 16 + gq);
            #pragma unroll
            for (int nj = 0; nj < 8; nj++) {
                const int col = nl + warp_n * 64 + nj * 8 + tq * 2;
                const float bv0 = bias[col], bv1 = bias[col + 1];
                split_store(H, L, row * Dm + col,
                            (acc[mi][nj][0] + bv0) * sc, (acc[mi][nj][1] + bv1) * sc);
                split_store(H, L, (row + 8) * Dm + col,
                            (acc[mi][nj][2] + bv0) * sc, (acc[mi][nj][3] + bv1) * sc);
            }
        }
    }
}

// ---------------- HMMA flash attention (unchanged from R7) ----------------
#define ATT_SMEM 65536
__device__ __forceinline__ uint32_t swo(int row, int e) {
    return (uint32_t)(((row >> 3) * 8 + (e >> 3)) * 128 + (((row & 7) ^ (e >> 3)) << 4));
}

__global__ __launch_bounds__(256) void fattn()
{
    extern __shared__ char sm[];
    const uint32_t sb = smem_u32(sm);
    const int tid = threadIdx.x, w = tid >> 5, lane = tid & 31;
    const int qb = gridDim.x - 1 - blockIdx.x;   // heavy tiles first
    const int h = blockIdx.y, b = blockIdx.z;
    const int q0 = qb * 128;
    const size_t tq0 = (size_t)b * Sq + q0;

    #pragma unroll
    for (int i = 0; i < 8; i++) {
        int sid = tid + 256 * i;
        int arr = sid >> 10, rc = sid & 1023, row = rc >> 3, c8 = rc & 7;
        const __nv_bfloat16* src = (arr ? g_ql : g_qh) + (tq0 + row) * Dm + h * 64 + c8 * 8;
        CP_ASYNC16(sb + arr * 16384 + (uint32_t)(((row >> 3) * 8 + c8) * 128
                   + (((row & 7) ^ c8) << 4)), src);
    }
    CP_COMMIT(); CP_WAIT0(); __syncthreads();

    uint32_t qh[4][4], ql[4][4];
    {
        int row = 16 * w + (lane & 7) + ((lane >> 3) & 1) * 8;
        #pragma unroll
        for (int ks = 0; ks < 4; ks++) {
            uint32_t off = swo(row, ks * 16 + (lane >> 4) * 8);
            ldmat4(qh[ks], sb + off);
            ldmat4(ql[ks], sb + 16384 + off);
        }
    }
    __syncthreads();

    float o[8][4], m[2] = {-1e30f, -1e30f}, l[2] = {0.f, 0.f};
    #pragma unroll
    for (int nj = 0; nj < 8; nj++)
        #pragma unroll
        for (int c = 0; c < 4; c++) o[nj][c] = 0.f;

    const int nkv = 2 * qb + 2;
    const size_t tb = (size_t)b * Sq;

    auto fillkv = [&](int st, int kt) {
        #pragma unroll
        for (int i = 0; i < 8; i++) {
            int sid = tid + 256 * i;
            int arr = sid >> 9, rc = sid & 511, row = rc >> 3, c8 = rc & 7;
            const __nv_bfloat16* s = (arr == 0 ? g_kh : arr == 1 ? g_kl :
                                      arr == 2 ? g_vh : g_vl);
            const __nv_bfloat16* src = s + (tb + kt * 64 + row) * Dm + h * 64 + c8 * 8;
            CP_ASYNC16(sb + st * 32768 + arr * 8192 + (uint32_t)(((row >> 3) * 8 + c8) * 128
                       + (((row & 7) ^ c8) << 4)), src);
        }
    };

    fillkv(0, 0); CP_COMMIT();

    for (int kt = 0; kt < nkv; kt++) {
        CP_WAIT0();
        __syncthreads();
        if (kt + 1 < nkv) { fillkv((kt + 1) & 1, kt + 1); CP_COMMIT(); }

        const uint32_t kbb = sb + (kt & 1) * 32768;
        float s[8][4];
        #pragma unroll
        for (int nj = 0; nj < 8; nj++)
            #pragma unroll
            for (int c = 0; c < 4; c++) s[nj][c] = 0.f;

        #pragma unroll
        for (int ks = 0; ks < 4; ks++) {
            #pragma unroll
            for (int njp = 0; njp < 4; njp++) {
                int krow = njp * 16 + (lane >> 4) * 8 + (lane & 7);
                uint32_t off = swo(krow, ks * 16 + ((lane >> 3) & 1) * 8);
                uint32_t kbh[4], kbl[4];
                ldmat4(kbh, kbb + off);
                ldmat4(kbl, kbb + 8192 + off);
                mma16816(s[2 * njp],     qh[ks], kbh[0], kbh[1]);
                mma16816(s[2 * njp + 1], qh[ks], kbh[2], kbh[3]);
                mma16816(s[2 * njp],     qh[ks], kbl[0], kbl[1]);
                mma16816(s[2 * njp + 1], qh[ks], kbl[2], kbl[3]);
                mma16816(s[2 * njp],     ql[ks], kbh[0], kbh[1]);
                mma16816(s[2 * njp + 1], ql[ks], kbh[2], kbh[3]);
            }
        }

        const int rowA = q0 + 16 * w + (lane >> 2);
        if (kt * 64 + 63 > q0 + 16 * w) {
            #pragma unroll
            for (int nj = 0; nj < 8; nj++)
                #pragma unroll
                for (int c = 0; c < 4; c++) {
                    int col = kt * 64 + nj * 8 + (lane & 3) * 2 + (c & 1);
                    if (col > rowA + (c >> 1) * 8) s[nj][c] = -1e30f;
                }
        }

        float mxA = -1e30f, mxB = -1e30f;
        #pragma unroll
        for (int nj = 0; nj < 8; nj++) {
            mxA = fmaxf(mxA, fmaxf(s[nj][0], s[nj][1]));
            mxB = fmaxf(mxB, fmaxf(s[nj][2], s[nj][3]));
        }
        #pragma unroll
        for (int off = 1; off < 4; off <<= 1) {
            mxA = fmaxf(mxA, __shfl_xor_sync(0xffffffffu, mxA, off));
            mxB = fmaxf(mxB, __shfl_xor_sync(0xffffffffu, mxB, off));
        }
        float mA = fmaxf(m[0], mxA), mB = fmaxf(m[1], mxB);
        float scA = fexp(m[0] - mA), scB = fexp(m[1] - mB);
        m[0] = mA; m[1] = mB;
        float sA = 0.f, sB = 0.f;
        #pragma unroll
        for (int nj = 0; nj < 8; nj++) {
            s[nj][0] = fexp(s[nj][0] - mA); s[nj][1] = fexp(s[nj][1] - mA);
            s[nj][2] = fexp(s[nj][2] - mB); s[nj][3] = fexp(s[nj][3] - mB);
            sA += s[nj][0] + s[nj][1];
            sB += s[nj][2] + s[nj][3];
        }
        #pragma unroll
        for (int off = 1; off < 4; off <<= 1) {
            sA += __shfl_xor_sync(0xffffffffu, sA, off);
            sB += __shfl_xor_sync(0xffffffffu, sB, off);
        }
        l[0] = l[0] * scA + sA;
        l[1] = l[1] * scB + sB;
        #pragma unroll
        for (int nj = 0; nj < 8; nj++) {
            o[nj][0] *= scA; o[nj][1] *= scA; o[nj][2] *= scB; o[nj][3] *= scB;
        }

        const uint32_t vbb = kbb + 16384;
        #pragma unroll
        for (int kk = 0; kk < 4; kk++) {
            uint32_t pah[4], pal[4];
            pack_pair(pah[0], pal[0], s[2 * kk][0],     s[2 * kk][1]);
            pack_pair(pah[1], pal[1], s[2 * kk][2],     s[2 * kk][3]);
            pack_pair(pah[2], pal[2], s[2 * kk + 1][0], s[2 * kk + 1][1]);
            pack_pair(pah[3], pal[3], s[2 * kk + 1][2], s[2 * kk + 1][3]);
            int vrow = kk * 16 + (lane & 7) + ((lane >> 3) & 1) * 8;
            #pragma unroll
            for (int ep = 0; ep < 4; ep++) {
                uint32_t off = swo(vrow, ep * 16 + (lane >> 4) * 8);
                uint32_t vbh[4], vbl[4];
                ldmat4t(vbh, vbb + off);
                ldmat4t(vbl, vbb + 8192 + off);
                mma16816(o[2 * ep],     pah, vbh[0], vbh[1]);
                mma16816(o[2 * ep + 1], pah, vbh[2], vbh[3]);
                mma16816(o[2 * ep],     pah, vbl[0], vbl[1]);
                mma16816(o[2 * ep + 1], pah, vbl[2], vbl[3]);
                mma16816(o[2 * ep],     pal, vbh[0], vbh[1]);
                mma16816(o[2 * ep + 1], pal, vbh[2], vbh[3]);
            }
        }
    }

    const float invA = 1.f / l[0], invB = 1.f / l[1];
    const size_t base = (tq0 + 16 * w + (lane >> 2)) * Dm + h * 64;
    #pragma unroll
    for (int nj = 0; nj < 8; nj++) {
        const int col = nj * 8 + (lane & 3) * 2;
        split_store(g_zh, g_zl, base + col,          o[nj][0] * invA, o[nj][1] * invA);
        split_store(g_zh, g_zl, base + 8 * Dm + col, o[nj][2] * invB, o[nj][3] * invB);
    }
}

// ---------------------------------------------------------------------------
extern "C" void kernel_launch(void* const* d_in, const int* in_sizes, int n_in,
                              void* d_out, int out_size)
{
    const float* x  = (const float*)d_in[0];
    const float* wq = (const float*)d_in[1];
    const float* bq = (const float*)d_in[2];
    const float* wk = (const float*)d_in[3];
    const float* bk = (const float*)d_in[4];
    const float* wv = (const float*)d_in[5];
    const float* bv = (const float*)d_in[6];
    const float* wo = (const float*)d_in[7];
    const float* bo = (const float*)d_in[8];
    float* out = (float*)d_out;

    cudaFuncSetAttribute(hmma_gemm, cudaFuncAttributeMaxDynamicSharedMemorySize, GEMM_SMEM);
    cudaFuncSetAttribute(fattn,     cudaFuncAttributeMaxDynamicSharedMemorySize, ATT_SMEM);

    void* p;
    cudaGetSymbolAddress(&p, g_xh); __nv_bfloat16* xh = (__nv_bfloat16*)p;
    cudaGetSymbolAddress(&p, g_xl); __nv_bfloat16* xl = (__nv_bfloat16*)p;
    cudaGetSymbolAddress(&p, g_zh); __nv_bfloat16* zh = (__nv_bfloat16*)p;
    cudaGetSymbolAddress(&p, g_zl); __nv_bfloat16* zl = (__nv_bfloat16*)p;
    cudaGetSymbolAddress(&p, g_wh); __nv_bfloat16* wh = (__nv_bfloat16*)p;
    cudaGetSymbolAddress(&p, g_wl); __nv_bfloat16* wl = (__nv_bfloat16*)p;
    cudaGetSymbolAddress(&p, g_oh); __nv_bfloat16* oh = (__nv_bfloat16*)p;
    cudaGetSymbolAddress(&p, g_ol); __nv_bfloat16* ol = (__nv_bfloat16*)p;

    conv_split<<<(Tt * Dm / 4 + 255) / 256, 256>>>(x, xh, xl, Tt * Dm / 4);
    conv_wqkv<<<(3 * Dm * Dm + 255) / 256, 256>>>(wq, wk, wv);
    conv_wo<<<(Dm * Dm + 255) / 256, 256>>>(wo);

    hmma_gemm<<<dim3(Tt / 128, 12), 256, GEMM_SMEM>>>(
        xh, xl, wh, wl, bq, bk, bv, nullptr, 1);

    fattn<<<dim3(Sq / 128, Hh, Bsz), 256, ATT_SMEM>>>();

    hmma_gemm<<<dim3(Tt / 128, 4), 256, GEMM_SMEM>>>(
        zh, zl, oh, ol, bo, bo, bo, out, 0);
}

// round 9
// speedup vs baseline: 1.0628x; 1.0628x over previous
#include <cuda_runtime.h>
#include <cuda_bf16.h>
#include <cstdint>

#define Bsz 4
#define Sq  2048
#define Dm  1024
#define Hh  16
#define Dh  64
#define Tt  (Bsz * Sq)

// ---------------- scratch ----------------
__device__ __nv_bfloat16 g_xh[(size_t)Tt * Dm];
__device__ __nv_bfloat16 g_xl[(size_t)Tt * Dm];
__device__ __nv_bfloat16 g_wh[(size_t)3 * Dm * Dm];
__device__ __nv_bfloat16 g_wl[(size_t)3 * Dm * Dm];
__device__ __nv_bfloat16 g_oh[(size_t)Dm * Dm];
__device__ __nv_bfloat16 g_ol[(size_t)Dm * Dm];
__device__ __nv_bfloat16 g_qh[(size_t)Tt * Dm];
__device__ __nv_bfloat16 g_ql[(size_t)Tt * Dm];
__device__ __nv_bfloat16 g_kh[(size_t)Tt * Dm];
__device__ __nv_bfloat16 g_kl[(size_t)Tt * Dm];
__device__ __nv_bfloat16 g_vh[(size_t)Tt * Dm];
__device__ __nv_bfloat16 g_vl[(size_t)Tt * Dm];
__device__ __nv_bfloat16 g_zh[(size_t)Tt * Dm];
__device__ __nv_bfloat16 g_zl[(size_t)Tt * Dm];

// ---------------- helpers (arch-stable PTX only) ----------------
__device__ __forceinline__ uint32_t smem_u32(const void* p) {
    uint32_t a;
    asm("{ .reg .u64 t; cvta.to.shared.u64 t, %1; cvt.u32.u64 %0, t; }" : "=r"(a) : "l"(p));
    return a;
}
#define CP_ASYNC16(dst, src) \
    asm volatile("cp.async.cg.shared.global [%0], [%1], 16;" :: "r"(dst), "l"(src))
#define CP_COMMIT() asm volatile("cp.async.commit_group;" ::: "memory")
#define CP_WAIT1()  asm volatile("cp.async.wait_group 1;" ::: "memory")
#define CP_WAIT0()  asm volatile("cp.async.wait_group 0;" ::: "memory")

__device__ __forceinline__ void ldmat4(uint32_t r[4], uint32_t a) {
    asm volatile("ldmatrix.sync.aligned.m8n8.x4.shared.b16 {%0,%1,%2,%3}, [%4];"
                 : "=r"(r[0]), "=r"(r[1]), "=r"(r[2]), "=r"(r[3]) : "r"(a));
}
__device__ __forceinline__ void ldmat4t(uint32_t r[4], uint32_t a) {
    asm volatile("ldmatrix.sync.aligned.m8n8.x4.trans.shared.b16 {%0,%1,%2,%3}, [%4];"
                 : "=r"(r[0]), "=r"(r[1]), "=r"(r[2]), "=r"(r[3]) : "r"(a));
}
__device__ __forceinline__ void mma16816(float* c, const uint32_t* a,
                                         uint32_t b0, uint32_t b1) {
    asm volatile("mma.sync.aligned.m16n8k16.row.col.f32.bf16.bf16.f32 "
                 "{%0,%1,%2,%3}, {%4,%5,%6,%7}, {%8,%9}, {%0,%1,%2,%3};"
                 : "+f"(c[0]), "+f"(c[1]), "+f"(c[2]), "+f"(c[3])
                 : "r"(a[0]), "r"(a[1]), "r"(a[2]), "r"(a[3]), "r"(b0), "r"(b1));
}
#define CVT2(res, hi, lo) \
    asm("cvt.rn.bf16x2.f32 %0, %1, %2;" : "=r"(res) : "f"(hi), "f"(lo))

__device__ __forceinline__ float fexp(float x) {
    x = fmaxf(x, -80.f);
    float t = x * 1.44269504f;
    float fk = t + 12582912.f;
    int   i  = __float_as_int(fk) - 0x4B400000;
    float f  = t - (fk - 12582912.f);
    float p = 1.33978e-3f;
    p = fmaf(p, f, 9.67839e-3f);
    p = fmaf(p, f, 5.55041e-2f);
    p = fmaf(p, f, 2.40227e-1f);
    p = fmaf(p, f, 6.93147e-1f);
    p = fmaf(p, f, 1.0f);
    return __int_as_float(__float_as_int(p) + (i << 23));
}
__device__ __forceinline__ void pack_pair(uint32_t& hv, uint32_t& lv, float v0, float v1) {
    CVT2(hv, v1, v0);
    float f0 = __uint_as_float(hv << 16);
    float f1 = __uint_as_float(hv & 0xFFFF0000u);
    CVT2(lv, v1 - f1, v0 - f0);
}
__device__ __forceinline__ void split_store(__nv_bfloat16* H, __nv_bfloat16* L,
                                            size_t idx, float v0, float v1) {
    uint32_t hv, lv;
    pack_pair(hv, lv, v0, v1);
    *(uint32_t*)(H + idx) = hv;
    *(uint32_t*)(L + idx) = lv;
}

// ---------------- prep ----------------
__global__ void conv_split(const float* __restrict__ in, __nv_bfloat16* __restrict__ hi,
                           __nv_bfloat16* __restrict__ lo, int n4)
{
    int i = blockIdx.x * blockDim.x + threadIdx.x;
    if (i >= n4) return;
    float4 v = ((const float4*)in)[i];
    uint32_t h0, h1, l0, l1;
    pack_pair(h0, l0, v.x, v.y);
    pack_pair(h1, l1, v.z, v.w);
    ((uint32_t*)hi)[2 * i] = h0; ((uint32_t*)hi)[2 * i + 1] = h1;
    ((uint32_t*)lo)[2 * i] = l0; ((uint32_t*)lo)[2 * i + 1] = l1;
}
__global__ void conv_wqkv(const float* __restrict__ wq, const float* __restrict__ wk,
                          const float* __restrict__ wv)
{
    int id = blockIdx.x * 256 + threadIdx.x;
    if (id >= 3 * Dm * Dm) return;
    int n = id >> 10, d = id & 1023;
    int proj = n >> 10, nl = n & 1023, h = nl >> 6, e = nl & 63;
    const float* W = (proj == 0 ? wq : proj == 1 ? wk : wv);
    float v = W[((size_t)h * Dm + d) * Dh + e];
    __nv_bfloat16 hh = __float2bfloat16(v);
    g_wh[id] = hh;
    g_wl[id] = __float2bfloat16(v - __bfloat162float(hh));
}
__global__ void conv_wo(const float* __restrict__ wo)
{
    int id = blockIdx.x * 256 + threadIdx.x;
    if (id >= Dm * Dm) return;
    int n = id >> 10, k = id & 1023;
    float v = wo[(size_t)k * Dm + n];
    __nv_bfloat16 hh = __float2bfloat16(v);
    g_oh[id] = hh;
    g_ol[id] = __float2bfloat16(v - __bfloat162float(hh));
}

// ---- bf16x3 HMMA GEMM: R7 config (128x128, warp 64x32, 3-stage, 2 CTA/SM) --
#define ARR_BYTES 8192
#define BUF_BYTES (4 * ARR_BYTES)
#define GEMM_SMEM (3 * BUF_BYTES)      /* 98304 */

__global__ __launch_bounds__(256, 2) void hmma_gemm(
    const __nv_bfloat16* __restrict__ Ah, const __nv_bfloat16* __restrict__ Al,
    const __nv_bfloat16* __restrict__ Bh, const __nv_bfloat16* __restrict__ Bl,
    const float* __restrict__ b0, const float* __restrict__ b1,
    const float* __restrict__ b2, float* __restrict__ C, int mode)
{
    extern __shared__ char smc[];
    const uint32_t sb = smem_u32(smc);
    const int tid = threadIdx.x, wid = tid >> 5, lane = tid & 31;
    const int warp_m = wid >> 2, warp_n = wid & 3;
    const int g = lane >> 3, r = lane & 7;
    const int m0  = blockIdx.x * 128;
    const int n0g = blockIdx.y * 128;
    const int proj = n0g >> 10;
    const int nl   = n0g & 1023;
    const float* bias = (proj == 0 ? b0 : proj == 1 ? b1 : b2);

    const __nv_bfloat16* srcs[4];
    srcs[0] = Ah + (size_t)m0  * Dm;
    srcs[1] = Al + (size_t)m0  * Dm;
    srcs[2] = Bh + (size_t)n0g * Dm;
    srcs[3] = Bl + (size_t)n0g * Dm;

    const uint32_t aoff0 = (uint32_t)(((warp_m * 8 + (g & 1)) * 4 + (g >> 1)) * 128 + r * 16);
    const uint32_t boff0 = (uint32_t)(((warp_n * 4 + (g >> 1)) * 4 + (g & 1)) * 128 + r * 16);

    auto fill = [&](int buf, int k0) {
        #pragma unroll
        for (int arr = 0; arr < 4; arr++) {
            uint32_t abase = sb + buf * BUF_BYTES + arr * ARR_BYTES;
            const __nv_bfloat16* s = srcs[arr];
            #pragma unroll
            for (int i = 0; i < 2; i++) {
                int cid = tid + 256 * i;
                int row = cid >> 2, kc = (cid & 3) * 8;
                CP_ASYNC16(abase + (uint32_t)(((row >> 3) * 4 + (kc >> 3)) * 128
                           + (row & 7) * 16),
                           s + (size_t)row * Dm + k0 + kc);
            }
        }
    };

    float acc[4][4][4];
    #pragma unroll
    for (int mi = 0; mi < 4; mi++)
        #pragma unroll
        for (int nj = 0; nj < 4; nj++)
            #pragma unroll
            for (int c = 0; c < 4; c++) acc[mi][nj][c] = 0.f;

    fill(0, 0);  CP_COMMIT();
    fill(1, 32); CP_COMMIT();

    const int NIT = Dm / 32;
    int buf = 0;
    for (int it = 0; it < NIT; it++) {
        if (it == NIT - 1) { CP_WAIT0(); } else { CP_WAIT1(); }
        __syncthreads();
        if (it + 2 < NIT) {
            int nb = buf + 2; if (nb >= 3) nb -= 3;
            fill(nb, (it + 2) * 32);
            CP_COMMIT();
        }

        const uint32_t bufb = sb + buf * BUF_BYTES;
        const uint32_t bAh = bufb, bAl = bufb + ARR_BYTES;
        const uint32_t bBh = bufb + 2 * ARR_BYTES, bBl = bufb + 3 * ARR_BYTES;

        #pragma unroll
        for (int ks = 0; ks < 2; ks++) {
            uint32_t afr[4][4];
            uint32_t bh[2][4], bl[2][4];
            ldmat4(bh[0], bBh + boff0 + ks * 256);
            ldmat4(bh[1], bBh + boff0 + 1024 + ks * 256);
            ldmat4(bl[0], bBl + boff0 + ks * 256);
            ldmat4(bl[1], bBl + boff0 + 1024 + ks * 256);
            #pragma unroll
            for (int mi = 0; mi < 4; mi++)
                ldmat4(afr[mi], bAh + aoff0 + mi * 1024 + ks * 256);
            #pragma unroll
            for (int mi = 0; mi < 4; mi++)
                #pragma unroll
                for (int nj = 0; nj < 4; nj++) {
                    mma16816(acc[mi][nj], afr[mi],
                             bh[nj >> 1][(nj & 1) * 2], bh[nj >> 1][(nj & 1) * 2 + 1]);
                    mma16816(acc[mi][nj], afr[mi],
                             bl[nj >> 1][(nj & 1) * 2], bl[nj >> 1][(nj & 1) * 2 + 1]);
                }
            #pragma unroll
            for (int mi = 0; mi < 4; mi++)
                ldmat4(afr[mi], bAl + aoff0 + mi * 1024 + ks * 256);
            #pragma unroll
            for (int mi = 0; mi < 4; mi++)
                #pragma unroll
                for (int nj = 0; nj < 4; nj++)
                    mma16816(acc[mi][nj], afr[mi],
                             bh[nj >> 1][(nj & 1) * 2], bh[nj >> 1][(nj & 1) * 2 + 1]);
        }
        if (++buf >= 3) buf = 0;
    }

    const int gq = lane >> 2, tq = lane & 3;
    if (mode == 0) {
        #pragma unroll
        for (int mi = 0; mi < 4; mi++) {
            const int row = m0 + warp_m * 64 + mi * 16 + gq;
            #pragma unroll
            for (int nj = 0; nj < 4; nj++) {
                const int col = nl + warp_n * 32 + nj * 8 + tq * 2;
                const float bv0 = bias[col], bv1 = bias[col + 1];
                *(float2*)(C + (size_t)row * Dm + col) =
                    make_float2(acc[mi][nj][0] + bv0, acc[mi][nj][1] + bv1);
                *(float2*)(C + (size_t)(row + 8) * Dm + col) =
                    make_float2(acc[mi][nj][2] + bv0, acc[mi][nj][3] + bv1);
            }
        }
    } else {
        __nv_bfloat16* H = (proj == 0 ? g_qh : proj == 1 ? g_kh : g_vh);
        __nv_bfloat16* L = (proj == 0 ? g_ql : proj == 1 ? g_kl : g_vl);
        const float sc = (proj == 0) ? 0.125f : 1.f;
        #pragma unroll
        for (int mi = 0; mi < 4; mi++) {
            const size_t row = (size_t)(m0 + warp_m * 64 + mi * 16 + gq);
            #pragma unroll
            for (int nj = 0; nj < 4; nj++) {
                const int col = nl + warp_n * 32 + nj * 8 + tq * 2;
                const float bv0 = bias[col], bv1 = bias[col + 1];
                split_store(H, L, row * Dm + col,
                            (acc[mi][nj][0] + bv0) * sc, (acc[mi][nj][1] + bv1) * sc);
                split_store(H, L, (row + 8) * Dm + col,
                            (acc[mi][nj][2] + bv0) * sc, (acc[mi][nj][3] + bv1) * sc);
            }
        }
    }
}

// ---------------- HMMA flash attention: KV tile 128, 1 sync/tile ------------
// smem: stage s at s*65536: Kh +0, Kl +16384, Vh +32768, Vl +49152 (128rx128B)
#define ATT_SMEM 131072
__device__ __forceinline__ uint32_t swo(int row, int e) {
    return (uint32_t)(((row >> 3) * 8 + (e >> 3)) * 128 + (((row & 7) ^ (e >> 3)) << 4));
}

__global__ __launch_bounds__(256) void fattn()
{
    extern __shared__ char sm[];
    const uint32_t sb = smem_u32(sm);
    const int tid = threadIdx.x, w = tid >> 5, lane = tid & 31;
    const int qb = gridDim.x - 1 - blockIdx.x;   // heavy tiles first
    const int h = blockIdx.y, b = blockIdx.z;
    const int q0 = qb * 128;
    const size_t tq0 = (size_t)b * Sq + q0;

    // stage Q hi/lo (128 rows x 64 cols) and pull into frags
    #pragma unroll
    for (int i = 0; i < 8; i++) {
        int sid = tid + 256 * i;
        int arr = sid >> 10, rc = sid & 1023, row = rc >> 3, c8 = rc & 7;
        const __nv_bfloat16* src = (arr ? g_ql : g_qh) + (tq0 + row) * Dm + h * 64 + c8 * 8;
        CP_ASYNC16(sb + arr * 16384 + swo(row, c8 * 8), src);
    }
    CP_COMMIT(); CP_WAIT0(); __syncthreads();

    uint32_t qh[4][4], ql[4][4];
    {
        int row = 16 * w + (lane & 7) + ((lane >> 3) & 1) * 8;
        #pragma unroll
        for (int ks = 0; ks < 4; ks++) {
            uint32_t off = swo(row, ks * 16 + (lane >> 4) * 8);
            ldmat4(qh[ks], sb + off);
            ldmat4(ql[ks], sb + 16384 + off);
        }
    }
    __syncthreads();

    float o[8][4], m[2] = {-1e30f, -1e30f}, l[2] = {0.f, 0.f};
    #pragma unroll
    for (int nj = 0; nj < 8; nj++)
        #pragma unroll
        for (int c = 0; c < 4; c++) o[nj][c] = 0.f;

    const int nkv = qb + 1;
    const size_t tb = (size_t)b * Sq;

    auto fillkv = [&](int st, int kt) {
        #pragma unroll
        for (int i = 0; i < 16; i++) {
            int sid = tid + 256 * i;
            int arr = sid >> 10, rc = sid & 1023, row = rc >> 3, c8 = rc & 7;
            const __nv_bfloat16* s = (arr == 0 ? g_kh : arr == 1 ? g_kl :
                                      arr == 2 ? g_vh : g_vl);
            const __nv_bfloat16* src = s + (tb + kt * 128 + row) * Dm + h * 64 + c8 * 8;
            CP_ASYNC16(sb + st * 65536 + arr * 16384 + swo(row, c8 * 8), src);
        }
    };

    fillkv(0, 0); CP_COMMIT();

    for (int kt = 0; kt < nkv; kt++) {
        CP_WAIT0();
        __syncthreads();
        if (kt + 1 < nkv) { fillkv((kt + 1) & 1, kt + 1); CP_COMMIT(); }

        const uint32_t kbb = sb + (kt & 1) * 65536;
        float s[16][4];
        #pragma unroll
        for (int nj = 0; nj < 16; nj++)
            #pragma unroll
            for (int c = 0; c < 4; c++) s[nj][c] = 0.f;

        // S = Qh*Kh + Qh*Kl + Ql*Kh   (128 kv rows)
        #pragma unroll
        for (int ks = 0; ks < 4; ks++) {
            #pragma unroll
            for (int njp = 0; njp < 8; njp++) {
                int krow = njp * 16 + (lane >> 4) * 8 + (lane & 7);
                uint32_t off = swo(krow, ks * 16 + ((lane >> 3) & 1) * 8);
                uint32_t kbh[4], kbl[4];
                ldmat4(kbh, kbb + off);
                ldmat4(kbl, kbb + 16384 + off);
                mma16816(s[2 * njp],     qh[ks], kbh[0], kbh[1]);
                mma16816(s[2 * njp + 1], qh[ks], kbh[2], kbh[3]);
                mma16816(s[2 * njp],     qh[ks], kbl[0], kbl[1]);
                mma16816(s[2 * njp + 1], qh[ks], kbl[2], kbl[3]);
                mma16816(s[2 * njp],     ql[ks], kbh[0], kbh[1]);
                mma16816(s[2 * njp + 1], ql[ks], kbh[2], kbh[3]);
            }
        }

        // causal mask (only the diagonal tile)
        if (kt == nkv - 1) {
            const int rowA = q0 + 16 * w + (lane >> 2);
            #pragma unroll
            for (int nj = 0; nj < 16; nj++)
                #pragma unroll
                for (int c = 0; c < 4; c++) {
                    int col = kt * 128 + nj * 8 + (lane & 3) * 2 + (c & 1);
                    if (col > rowA + (c >> 1) * 8) s[nj][c] = -1e30f;
                }
        }

        float mxA = -1e30f, mxB = -1e30f;
        #pragma unroll
        for (int nj = 0; nj < 16; nj++) {
            mxA = fmaxf(mxA, fmaxf(s[nj][0], s[nj][1]));
            mxB = fmaxf(mxB, fmaxf(s[nj][2], s[nj][3]));
        }
        #pragma unroll
        for (int off = 1; off < 4; off <<= 1) {
            mxA = fmaxf(mxA, __shfl_xor_sync(0xffffffffu, mxA, off));
            mxB = fmaxf(mxB, __shfl_xor_sync(0xffffffffu, mxB, off));
        }
        float mA = fmaxf(m[0], mxA), mB = fmaxf(m[1], mxB);
        float scA = fexp(m[0] - mA), scB = fexp(m[1] - mB);
        m[0] = mA; m[1] = mB;
        float sA = 0.f, sB = 0.f;
        #pragma unroll
        for (int nj = 0; nj < 16; nj++) {
            s[nj][0] = fexp(s[nj][0] - mA); s[nj][1] = fexp(s[nj][1] - mA);
            s[nj][2] = fexp(s[nj][2] - mB); s[nj][3] = fexp(s[nj][3] - mB);
            sA += s[nj][0] + s[nj][1];
            sB += s[nj][2] + s[nj][3];
        }
        #pragma unroll
        for (int off = 1; off < 4; off <<= 1) {
            sA += __shfl_xor_sync(0xffffffffu, sA, off);
            sB += __shfl_xor_sync(0xffffffffu, sB, off);
        }
        l[0] = l[0] * scA + sA;
        l[1] = l[1] * scB + sB;
        #pragma unroll
        for (int nj = 0; nj < 8; nj++) {
            o[nj][0] *= scA; o[nj][1] *= scA; o[nj][2] *= scB; o[nj][3] *= scB;
        }

        // O += Ph*Vh + Ph*Vl + Pl*Vh   (kv dim 128 = 8 kk steps)
        const uint32_t vbb = kbb + 32768;
        #pragma unroll
        for (int kk = 0; kk < 8; kk++) {
            uint32_t pah[4], pal[4];
            pack_pair(pah[0], pal[0], s[2 * kk][0],     s[2 * kk][1]);
            pack_pair(pah[1], pal[1], s[2 * kk][2],     s[2 * kk][3]);
            pack_pair(pah[2], pal[2], s[2 * kk + 1][0], s[2 * kk + 1][1]);
            pack_pair(pah[3], pal[3], s[2 * kk + 1][2], s[2 * kk + 1][3]);
            int vrow = kk * 16 + (lane & 7) + ((lane >> 3) & 1) * 8;
            #pragma unroll
            for (int ep = 0; ep < 4; ep++) {
                uint32_t off = swo(vrow, ep * 16 + (lane >> 4) * 8);
                uint32_t vbh[4], vbl[4];
                ldmat4t(vbh, vbb + off);
                ldmat4t(vbl, vbb + 16384 + off);
                mma16816(o[2 * ep],     pah, vbh[0], vbh[1]);
                mma16816(o[2 * ep + 1], pah, vbh[2], vbh[3]);
                mma16816(o[2 * ep],     pah, vbl[0], vbl[1]);
                mma16816(o[2 * ep + 1], pah, vbl[2], vbl[3]);
                mma16816(o[2 * ep],     pal, vbh[0], vbh[1]);
                mma16816(o[2 * ep + 1], pal, vbh[2], vbh[3]);
            }
        }
    }

    const float invA = 1.f / l[0], invB = 1.f / l[1];
    const size_t base = (tq0 + 16 * w + (lane >> 2)) * Dm + h * 64;
    #pragma unroll
    for (int nj = 0; nj < 8; nj++) {
        const int col = nj * 8 + (lane & 3) * 2;
        split_store(g_zh, g_zl, base + col,          o[nj][0] * invA, o[nj][1] * invA);
        split_store(g_zh, g_zl, base + 8 * Dm + col, o[nj][2] * invB, o[nj][3] * invB);
    }
}

// ---------------------------------------------------------------------------
extern "C" void kernel_launch(void* const* d_in, const int* in_sizes, int n_in,
                              void* d_out, int out_size)
{
    const float* x  = (const float*)d_in[0];
    const float* wq = (const float*)d_in[1];
    const float* bq = (const float*)d_in[2];
    const float* wk = (const float*)d_in[3];
    const float* bk = (const float*)d_in[4];
    const float* wv = (const float*)d_in[5];
    const float* bv = (const float*)d_in[6];
    const float* wo = (const float*)d_in[7];
    const float* bo = (const float*)d_in[8];
    float* out = (float*)d_out;

    cudaFuncSetAttribute(hmma_gemm, cudaFuncAttributeMaxDynamicSharedMemorySize, GEMM_SMEM);
    cudaFuncSetAttribute(fattn,     cudaFuncAttributeMaxDynamicSharedMemorySize, ATT_SMEM);

    void* p;
    cudaGetSymbolAddress(&p, g_xh); __nv_bfloat16* xh = (__nv_bfloat16*)p;
    cudaGetSymbolAddress(&p, g_xl); __nv_bfloat16* xl = (__nv_bfloat16*)p;
    cudaGetSymbolAddress(&p, g_zh); __nv_bfloat16* zh = (__nv_bfloat16*)p;
    cudaGetSymbolAddress(&p, g_zl); __nv_bfloat16* zl = (__nv_bfloat16*)p;
    cudaGetSymbolAddress(&p, g_wh); __nv_bfloat16* wh = (__nv_bfloat16*)p;
    cudaGetSymbolAddress(&p, g_wl); __nv_bfloat16* wl = (__nv_bfloat16*)p;
    cudaGetSymbolAddress(&p, g_oh); __nv_bfloat16* oh = (__nv_bfloat16*)p;
    cudaGetSymbolAddress(&p, g_ol); __nv_bfloat16* ol = (__nv_bfloat16*)p;

    conv_split<<<(Tt * Dm / 4 + 255) / 256, 256>>>(x, xh, xl, Tt * Dm / 4);
    conv_wqkv<<<(3 * Dm * Dm + 255) / 256, 256>>>(wq, wk, wv);
    conv_wo<<<(Dm * Dm + 255) / 256, 256>>>(wo);

    hmma_gemm<<<dim3(Tt / 128, 24), 256, GEMM_SMEM>>>(
        xh, xl, wh, wl, bq, bk, bv, nullptr, 1);

    fattn<<<dim3(Sq / 128, Hh, Bsz), 256, ATT_SMEM>>>();

    hmma_gemm<<<dim3(Tt / 128, 8), 256, GEMM_SMEM>>>(
        zh, zl, oh, ol, bo, bo, bo, out, 0);
}

// round 10
// speedup vs baseline: 1.4094x; 1.3261x over previous
#include <cuda_runtime.h>
#include <cuda_fp16.h>
#include <cstdint>

#define Bsz 4
#define Sq  2048
#define Dm  1024
#define Hh  16
#define Dh  64
#define Tt  (Bsz * Sq)

// ---------------- scratch (fp16 split: right operands hi+lo, left hi only) --
__device__ __half g_xh[(size_t)Tt * Dm];
__device__ __half g_wh[(size_t)3 * Dm * Dm];
__device__ __half g_wl[(size_t)3 * Dm * Dm];
__device__ __half g_oh[(size_t)Dm * Dm];
__device__ __half g_ol[(size_t)Dm * Dm];
__device__ __half g_qh[(size_t)Tt * Dm];
__device__ __half g_kh[(size_t)Tt * Dm];
__device__ __half g_kl[(size_t)Tt * Dm];
__device__ __half g_vh[(size_t)Tt * Dm];
__device__ __half g_vl[(size_t)Tt * Dm];
__device__ __half g_zh[(size_t)Tt * Dm];

// ---------------- helpers (arch-stable PTX only) ----------------
__device__ __forceinline__ uint32_t smem_u32(const void* p) {
    uint32_t a;
    asm("{ .reg .u64 t; cvta.to.shared.u64 t, %1; cvt.u32.u64 %0, t; }" : "=r"(a) : "l"(p));
    return a;
}
#define CP_ASYNC16(dst, src) \
    asm volatile("cp.async.cg.shared.global [%0], [%1], 16;" :: "r"(dst), "l"(src))
#define CP_COMMIT() asm volatile("cp.async.commit_group;" ::: "memory")
#define CP_WAIT1()  asm volatile("cp.async.wait_group 1;" ::: "memory")
#define CP_WAIT0()  asm volatile("cp.async.wait_group 0;" ::: "memory")

__device__ __forceinline__ void ldmat4(uint32_t r[4], uint32_t a) {
    asm volatile("ldmatrix.sync.aligned.m8n8.x4.shared.b16 {%0,%1,%2,%3}, [%4];"
                 : "=r"(r[0]), "=r"(r[1]), "=r"(r[2]), "=r"(r[3]) : "r"(a));
}
__device__ __forceinline__ void ldmat4t(uint32_t r[4], uint32_t a) {
    asm volatile("ldmatrix.sync.aligned.m8n8.x4.trans.shared.b16 {%0,%1,%2,%3}, [%4];"
                 : "=r"(r[0]), "=r"(r[1]), "=r"(r[2]), "=r"(r[3]) : "r"(a));
}
__device__ __forceinline__ void mma16816(float* c, const uint32_t* a,
                                         uint32_t b0, uint32_t b1) {
    asm volatile("mma.sync.aligned.m16n8k16.row.col.f32.f16.f16.f32 "
                 "{%0,%1,%2,%3}, {%4,%5,%6,%7}, {%8,%9}, {%0,%1,%2,%3};"
                 : "+f"(c[0]), "+f"(c[1]), "+f"(c[2]), "+f"(c[3])
                 : "r"(a[0]), "r"(a[1]), "r"(a[2]), "r"(a[3]), "r"(b0), "r"(b1));
}
// pack: low half <- lo, high half <- hi
#define CVTH2(res, hi, lo) \
    asm("cvt.rn.f16x2.f32 %0, %1, %2;" : "=r"(res) : "f"(hi), "f"(lo))

__device__ __forceinline__ float fexp(float x) {
    x = fmaxf(x, -80.f);
    float t = x * 1.44269504f;
    float fk = t + 12582912.f;
    int   i  = __float_as_int(fk) - 0x4B400000;
    float f  = t - (fk - 12582912.f);
    float p = 1.33978e-3f;
    p = fmaf(p, f, 9.67839e-3f);
    p = fmaf(p, f, 5.55041e-2f);
    p = fmaf(p, f, 2.40227e-1f);
    p = fmaf(p, f, 6.93147e-1f);
    p = fmaf(p, f, 1.0f);
    return __int_as_float(__float_as_int(p) + (i << 23));
}
__device__ __forceinline__ void split_pair(uint32_t& hv, uint32_t& lv, float v0, float v1) {
    CVTH2(hv, v1, v0);
    __half2 h2 = *(__half2*)&hv;
    CVTH2(lv, v1 - __high2float(h2), v0 - __low2float(h2));
}

// ---------------- prep ----------------
__global__ void conv_h(const float* __restrict__ in, __half* __restrict__ hi, int n4)
{
    int i = blockIdx.x * blockDim.x + threadIdx.x;
    if (i >= n4) return;
    float4 v = ((const float4*)in)[i];
    uint32_t h0, h1;
    CVTH2(h0, v.y, v.x);
    CVTH2(h1, v.w, v.z);
    ((uint32_t*)hi)[2 * i] = h0; ((uint32_t*)hi)[2 * i + 1] = h1;
}
__global__ void conv_wqkv(const float* __restrict__ wq, const float* __restrict__ wk,
                          const float* __restrict__ wv)
{
    int id = blockIdx.x * 256 + threadIdx.x;
    if (id >= 3 * Dm * Dm) return;
    int n = id >> 10, d = id & 1023;
    int proj = n >> 10, nl = n & 1023, h = nl >> 6, e = nl & 63;
    const float* W = (proj == 0 ? wq : proj == 1 ? wk : wv);
    float v = W[((size_t)h * Dm + d) * Dh + e];
    __half hh = __float2half_rn(v);
    g_wh[id] = hh;
    g_wl[id] = __float2half_rn(v - __half2float(hh));
}
__global__ void conv_wo(const float* __restrict__ wo)
{
    int id = blockIdx.x * 256 + threadIdx.x;
    if (id >= Dm * Dm) return;
    int n = id >> 10, k = id & 1023;
    float v = wo[(size_t)k * Dm + n];
    __half hh = __float2half_rn(v);
    g_oh[id] = hh;
    g_ol[id] = __float2half_rn(v - __half2float(hh));
}

// ---- fp16x2 HMMA GEMM: C = A_h * (B_h + B_l)^T + bias; 128x128, 2 CTA/SM ---
#define ARR_BYTES 8192
#define STG_BYTES (3 * ARR_BYTES)      /* A, Bh, Bl */
#define GEMM_SMEM (3 * STG_BYTES)      /* 73728 */

__global__ __launch_bounds__(256, 2) void hmma_gemm(
    const __half* __restrict__ A,
    const __half* __restrict__ Bh, const __half* __restrict__ Bl,
    const float* __restrict__ b0, const float* __restrict__ b1,
    const float* __restrict__ b2, float* __restrict__ C, int mode)
{
    extern __shared__ char smc[];
    const uint32_t sb = smem_u32(smc);
    const int tid = threadIdx.x, wid = tid >> 5, lane = tid & 31;
    const int warp_m = wid >> 2, warp_n = wid & 3;
    const int g = lane >> 3, r = lane & 7;
    const int m0  = blockIdx.x * 128;
    const int n0g = blockIdx.y * 128;
    const int proj = n0g >> 10;
    const int nl   = n0g & 1023;
    const float* bias = (proj == 0 ? b0 : proj == 1 ? b1 : b2);

    const __half* srcs[3];
    srcs[0] = A  + (size_t)m0  * Dm;
    srcs[1] = Bh + (size_t)n0g * Dm;
    srcs[2] = Bl + (size_t)n0g * Dm;

    const uint32_t aoff0 = (uint32_t)(((warp_m * 8 + (g & 1)) * 4 + (g >> 1)) * 128 + r * 16);
    const uint32_t boff0 = (uint32_t)(((warp_n * 4 + (g >> 1)) * 4 + (g & 1)) * 128 + r * 16);

    auto fill = [&](int buf, int k0) {
        #pragma unroll
        for (int arr = 0; arr < 3; arr++) {
            uint32_t abase = sb + buf * STG_BYTES + arr * ARR_BYTES;
            const __half* s = srcs[arr];
            #pragma unroll
            for (int i = 0; i < 2; i++) {
                int cid = tid + 256 * i;
                int row = cid >> 2, kc = (cid & 3) * 8;
                CP_ASYNC16(abase + (uint32_t)(((row >> 3) * 4 + (kc >> 3)) * 128
                           + (row & 7) * 16),
                           s + (size_t)row * Dm + k0 + kc);
            }
        }
    };

    float acc[4][4][4];
    #pragma unroll
    for (int mi = 0; mi < 4; mi++)
        #pragma unroll
        for (int nj = 0; nj < 4; nj++)
            #pragma unroll
            for (int c = 0; c < 4; c++) acc[mi][nj][c] = 0.f;

    fill(0, 0);  CP_COMMIT();
    fill(1, 32); CP_COMMIT();

    const int NIT = Dm / 32;
    int buf = 0;
    for (int it = 0; it < NIT; it++) {
        if (it == NIT - 1) { CP_WAIT0(); } else { CP_WAIT1(); }
        __syncthreads();
        if (it + 2 < NIT) {
            int nb = buf + 2; if (nb >= 3) nb -= 3;
            fill(nb, (it + 2) * 32);
            CP_COMMIT();
        }

        const uint32_t stb = sb + buf * STG_BYTES;
        const uint32_t bA = stb, bBh = stb + ARR_BYTES, bBl = stb + 2 * ARR_BYTES;

        #pragma unroll
        for (int ks = 0; ks < 2; ks++) {
            uint32_t afr[4][4];
            uint32_t bh[2][4], bl[2][4];
            ldmat4(bh[0], bBh + boff0 + ks * 256);
            ldmat4(bh[1], bBh + boff0 + 1024 + ks * 256);
            ldmat4(bl[0], bBl + boff0 + ks * 256);
            ldmat4(bl[1], bBl + boff0 + 1024 + ks * 256);
            #pragma unroll
            for (int mi = 0; mi < 4; mi++)
                ldmat4(afr[mi], bA + aoff0 + mi * 1024 + ks * 256);
            #pragma unroll
            for (int mi = 0; mi < 4; mi++)
                #pragma unroll
                for (int nj = 0; nj < 4; nj++) {
                    mma16816(acc[mi][nj], afr[mi],
                             bh[nj >> 1][(nj & 1) * 2], bh[nj >> 1][(nj & 1) * 2 + 1]);
                    mma16816(acc[mi][nj], afr[mi],
                             bl[nj >> 1][(nj & 1) * 2], bl[nj >> 1][(nj & 1) * 2 + 1]);
                }
        }
        if (++buf >= 3) buf = 0;
    }

    const int gq = lane >> 2, tq = lane & 3;
    if (mode == 0) {
        #pragma unroll
        for (int mi = 0; mi < 4; mi++) {
            const int row = m0 + warp_m * 64 + mi * 16 + gq;
            #pragma unroll
            for (int nj = 0; nj < 4; nj++) {
                const int col = nl + warp_n * 32 + nj * 8 + tq * 2;
                const float bv0 = bias[col], bv1 = bias[col + 1];
                *(float2*)(C + (size_t)row * Dm + col) =
                    make_float2(acc[mi][nj][0] + bv0, acc[mi][nj][1] + bv1);
                *(float2*)(C + (size_t)(row + 8) * Dm + col) =
                    make_float2(acc[mi][nj][2] + bv0, acc[mi][nj][3] + bv1);
            }
        }
    } else {
        #pragma unroll
        for (int mi = 0; mi < 4; mi++) {
            const size_t row = (size_t)(m0 + warp_m * 64 + mi * 16 + gq);
            #pragma unroll
            for (int nj = 0; nj < 4; nj++) {
                const int col = nl + warp_n * 32 + nj * 8 + tq * 2;
                const float bv0 = bias[col], bv1 = bias[col + 1];
                float a0 = acc[mi][nj][0] + bv0, a1 = acc[mi][nj][1] + bv1;
                float a2 = acc[mi][nj][2] + bv0, a3 = acc[mi][nj][3] + bv1;
                if (proj == 0) {        // Q: single fp16, scale 0.125
                    uint32_t hv;
                    CVTH2(hv, a1 * 0.125f, a0 * 0.125f);
                    *(uint32_t*)(g_qh + row * Dm + col) = hv;
                    CVTH2(hv, a3 * 0.125f, a2 * 0.125f);
                    *(uint32_t*)(g_qh + (row + 8) * Dm + col) = hv;
                } else {                // K/V: split hi/lo
                    __half* H = (proj == 1) ? g_kh : g_vh;
                    __half* L = (proj == 1) ? g_kl : g_vl;
                    uint32_t hv, lv;
                    split_pair(hv, lv, a0, a1);
                    *(uint32_t*)(H + row * Dm + col) = hv;
                    *(uint32_t*)(L + row * Dm + col) = lv;
                    split_pair(hv, lv, a2, a3);
                    *(uint32_t*)(H + (row + 8) * Dm + col) = hv;
                    *(uint32_t*)(L + (row + 8) * Dm + col) = lv;
                }
            }
        }
    }
}

// ---------------- fp16x2 HMMA flash attention: KV tile 128 ------------------
#define ATT_SMEM 131072
__device__ __forceinline__ uint32_t swo(int row, int e) {
    return (uint32_t)(((row >> 3) * 8 + (e >> 3)) * 128 + (((row & 7) ^ (e >> 3)) << 4));
}

__global__ __launch_bounds__(256) void fattn()
{
    extern __shared__ char sm[];
    const uint32_t sb = smem_u32(sm);
    const int tid = threadIdx.x, w = tid >> 5, lane = tid & 31;
    const int qb = gridDim.x - 1 - blockIdx.x;   // heavy tiles first
    const int h = blockIdx.y, b = blockIdx.z;
    const int q0 = qb * 128;
    const size_t tq0 = (size_t)b * Sq + q0;

    // stage Q (hi only, 128x64 fp16 = 16KB) and pull into frags
    #pragma unroll
    for (int i = 0; i < 4; i++) {
        int sid = tid + 256 * i;
        int row = sid >> 3, c8 = sid & 7;
        CP_ASYNC16(sb + swo(row, c8 * 8),
                   g_qh + (tq0 + row) * Dm + h * 64 + c8 * 8);
    }
    CP_COMMIT(); CP_WAIT0(); __syncthreads();

    uint32_t qh[4][4];
    {
        int row = 16 * w + (lane & 7) + ((lane >> 3) & 1) * 8;
        #pragma unroll
        for (int ks = 0; ks < 4; ks++)
            ldmat4(qh[ks], sb + swo(row, ks * 16 + (lane >> 4) * 8));
    }
    __syncthreads();

    float o[8][4], m[2] = {-1e30f, -1e30f}, l[2] = {0.f, 0.f};
    #pragma unroll
    for (int nj = 0; nj < 8; nj++)
        #pragma unroll
        for (int c = 0; c < 4; c++) o[nj][c] = 0.f;

    const int nkv = qb + 1;
    const size_t tb = (size_t)b * Sq;

    auto fillkv = [&](int st, int kt) {
        #pragma unroll
        for (int i = 0; i < 16; i++) {
            int sid = tid + 256 * i;
            int arr = sid >> 10, rc = sid & 1023, row = rc >> 3, c8 = rc & 7;
            const __half* s = (arr == 0 ? g_kh : arr == 1 ? g_kl :
                               arr == 2 ? g_vh : g_vl);
            CP_ASYNC16(sb + st * 65536 + arr * 16384 + swo(row, c8 * 8),
                       s + (tb + kt * 128 + row) * Dm + h * 64 + c8 * 8);
        }
    };

    fillkv(0, 0); CP_COMMIT();

    for (int kt = 0; kt < nkv; kt++) {
        CP_WAIT0();
        __syncthreads();
        if (kt + 1 < nkv) { fillkv((kt + 1) & 1, kt + 1); CP_COMMIT(); }

        const uint32_t kbb = sb + (kt & 1) * 65536;
        float s[16][4];
        #pragma unroll
        for (int nj = 0; nj < 16; nj++)
            #pragma unroll
            for (int c = 0; c < 4; c++) s[nj][c] = 0.f;

        // S = Qh * (Kh + Kl)
        #pragma unroll
        for (int ks = 0; ks < 4; ks++) {
            #pragma unroll
            for (int njp = 0; njp < 8; njp++) {
                int krow = njp * 16 + (lane >> 4) * 8 + (lane & 7);
                uint32_t off = swo(krow, ks * 16 + ((lane >> 3) & 1) * 8);
                uint32_t kbh[4], kbl[4];
                ldmat4(kbh, kbb + off);
                ldmat4(kbl, kbb + 16384 + off);
                mma16816(s[2 * njp],     qh[ks], kbh[0], kbh[1]);
                mma16816(s[2 * njp + 1], qh[ks], kbh[2], kbh[3]);
                mma16816(s[2 * njp],     qh[ks], kbl[0], kbl[1]);
                mma16816(s[2 * njp + 1], qh[ks], kbl[2], kbl[3]);
            }
        }

        if (kt == nkv - 1) {   // causal mask on diagonal tile
            const int rowA = q0 + 16 * w + (lane >> 2);
            #pragma unroll
            for (int nj = 0; nj < 16; nj++)
                #pragma unroll
                for (int c = 0; c < 4; c++) {
                    int col = kt * 128 + nj * 8 + (lane & 3) * 2 + (c & 1);
                    if (col > rowA + (c >> 1) * 8) s[nj][c] = -1e30f;
                }
        }

        float mxA = -1e30f, mxB = -1e30f;
        #pragma unroll
        for (int nj = 0; nj < 16; nj++) {
            mxA = fmaxf(mxA, fmaxf(s[nj][0], s[nj][1]));
            mxB = fmaxf(mxB, fmaxf(s[nj][2], s[nj][3]));
        }
        #pragma unroll
        for (int off = 1; off < 4; off <<= 1) {
            mxA = fmaxf(mxA, __shfl_xor_sync(0xffffffffu, mxA, off));
            mxB = fmaxf(mxB, __shfl_xor_sync(0xffffffffu, mxB, off));
        }
        float mA = fmaxf(m[0], mxA), mB = fmaxf(m[1], mxB);
        float scA = fexp(m[0] - mA), scB = fexp(m[1] - mB);
        m[0] = mA; m[1] = mB;
        float sA = 0.f, sB = 0.f;
        #pragma unroll
        for (int nj = 0; nj < 16; nj++) {
            s[nj][0] = fexp(s[nj][0] - mA); s[nj][1] = fexp(s[nj][1] - mA);
            s[nj][2] = fexp(s[nj][2] - mB); s[nj][3] = fexp(s[nj][3] - mB);
            sA += s[nj][0] + s[nj][1];
            sB += s[nj][2] + s[nj][3];
        }
        #pragma unroll
        for (int off = 1; off < 4; off <<= 1) {
            sA += __shfl_xor_sync(0xffffffffu, sA, off);
            sB += __shfl_xor_sync(0xffffffffu, sB, off);
        }
        l[0] = l[0] * scA + sA;
        l[1] = l[1] * scB + sB;
        #pragma unroll
        for (int nj = 0; nj < 8; nj++) {
            o[nj][0] *= scA; o[nj][1] *= scA; o[nj][2] *= scB; o[nj][3] *= scB;
        }

        // O += Ph * (Vh + Vl)
        const uint32_t vbb = kbb + 32768;
        #pragma unroll
        for (int kk = 0; kk < 8; kk++) {
            uint32_t pah[4];
            CVTH2(pah[0], s[2 * kk][1],     s[2 * kk][0]);
            CVTH2(pah[1], s[2 * kk][3],     s[2 * kk][2]);
            CVTH2(pah[2], s[2 * kk + 1][1], s[2 * kk + 1][0]);
            CVTH2(pah[3], s[2 * kk + 1][3], s[2 * kk + 1][2]);
            int vrow = kk * 16 + (lane & 7) + ((lane >> 3) & 1) * 8;
            #pragma unroll
            for (int ep = 0; ep < 4; ep++) {
                uint32_t off = swo(vrow, ep * 16 + (lane >> 4) * 8);
                uint32_t vbh[4], vbl[4];
                ldmat4t(vbh, vbb + off);
                ldmat4t(vbl, vbb + 16384 + off);
                mma16816(o[2 * ep],     pah, vbh[0], vbh[1]);
                mma16816(o[2 * ep + 1], pah, vbh[2], vbh[3]);
                mma16816(o[2 * ep],     pah, vbl[0], vbl[1]);
                mma16816(o[2 * ep + 1], pah, vbl[2], vbl[3]);
            }
        }
    }

    const float invA = 1.f / l[0], invB = 1.f / l[1];
    const size_t base = (tq0 + 16 * w + (lane >> 2)) * Dm + h * 64;
    #pragma unroll
    for (int nj = 0; nj < 8; nj++) {
        const int col = nj * 8 + (lane & 3) * 2;
        uint32_t p0, p1;
        CVTH2(p0, o[nj][1] * invA, o[nj][0] * invA);
        CVTH2(p1, o[nj][3] * invB, o[nj][2] * invB);
        *(uint32_t*)(g_zh + base + col)          = p0;
        *(uint32_t*)(g_zh + base + 8 * Dm + col) = p1;
    }
}

// ---------------------------------------------------------------------------
extern "C" void kernel_launch(void* const* d_in, const int* in_sizes, int n_in,
                              void* d_out, int out_size)
{
    const float* x  = (const float*)d_in[0];
    const float* wq = (const float*)d_in[1];
    const float* bq = (const float*)d_in[2];
    const float* wk = (const float*)d_in[3];
    const float* bk = (const float*)d_in[4];
    const float* wv = (const float*)d_in[5];
    const float* bv = (const float*)d_in[6];
    const float* wo = (const float*)d_in[7];
    const float* bo = (const float*)d_in[8];
    float* out = (float*)d_out;

    cudaFuncSetAttribute(hmma_gemm, cudaFuncAttributeMaxDynamicSharedMemorySize, GEMM_SMEM);
    cudaFuncSetAttribute(fattn,     cudaFuncAttributeMaxDynamicSharedMemorySize, ATT_SMEM);

    void* p;
    cudaGetSymbolAddress(&p, g_xh); __half* xh = (__half*)p;
    cudaGetSymbolAddress(&p, g_zh); __half* zh = (__half*)p;
    cudaGetSymbolAddress(&p, g_wh); __half* wh = (__half*)p;
    cudaGetSymbolAddress(&p, g_wl); __half* wl = (__half*)p;
    cudaGetSymbolAddress(&p, g_oh); __half* oh = (__half*)p;
    cudaGetSymbolAddress(&p, g_ol); __half* ol = (__half*)p;

    conv_h<<<(Tt * Dm / 4 + 255) / 256, 256>>>(x, xh, Tt * Dm / 4);
    conv_wqkv<<<(3 * Dm * Dm + 255) / 256, 256>>>(wq, wk, wv);
    conv_wo<<<(Dm * Dm + 255) / 256, 256>>>(wo);

    // QKV projection -> Q (fp16, x0.125), K/V (fp16 hi/lo)
    hmma_gemm<<<dim3(Tt / 128, 24), 256, GEMM_SMEM>>>(
        xh, wh, wl, bq, bk, bv, nullptr, 1);

    // flash attention -> z (fp16)
    fattn<<<dim3(Sq / 128, Hh, Bsz), 256, ATT_SMEM>>>();

    // output projection -> fp32 out
    hmma_gemm<<<dim3(Tt / 128, 8), 256, GEMM_SMEM>>>(
        zh, oh, ol, bo, bo, bo, out, 0);
}

// round 11
// speedup vs baseline: 2.1460x; 1.5227x over previous
#include <cuda_runtime.h>
#include <cuda_fp16.h>
#include <cstdint>

#define Bsz 4
#define Sq  2048
#define Dm  1024
#define Hh  16
#define Dh  64
#define Tt  (Bsz * Sq)

// ---------------- scratch (all single fp16) ----------------
__device__ __half g_xh[(size_t)Tt * Dm];
__device__ __half g_wh[(size_t)3 * Dm * Dm];
__device__ __half g_oh[(size_t)Dm * Dm];
__device__ __half g_qh[(size_t)Tt * Dm];
__device__ __half g_kh[(size_t)Tt * Dm];
__device__ __half g_vh[(size_t)Tt * Dm];
__device__ __half g_zh[(size_t)Tt * Dm];

// ---------------- helpers (arch-stable PTX only) ----------------
__device__ __forceinline__ uint32_t smem_u32(const void* p) {
    uint32_t a;
    asm("{ .reg .u64 t; cvta.to.shared.u64 t, %1; cvt.u32.u64 %0, t; }" : "=r"(a) : "l"(p));
    return a;
}
#define CP_ASYNC16(dst, src) \
    asm volatile("cp.async.cg.shared.global [%0], [%1], 16;" :: "r"(dst), "l"(src))
#define CP_COMMIT() asm volatile("cp.async.commit_group;" ::: "memory")
#define CP_WAIT1()  asm volatile("cp.async.wait_group 1;" ::: "memory")
#define CP_WAIT0()  asm volatile("cp.async.wait_group 0;" ::: "memory")

__device__ __forceinline__ void ldmat4(uint32_t r[4], uint32_t a) {
    asm volatile("ldmatrix.sync.aligned.m8n8.x4.shared.b16 {%0,%1,%2,%3}, [%4];"
                 : "=r"(r[0]), "=r"(r[1]), "=r"(r[2]), "=r"(r[3]) : "r"(a));
}
__device__ __forceinline__ void ldmat4t(uint32_t r[4], uint32_t a) {
    asm volatile("ldmatrix.sync.aligned.m8n8.x4.trans.shared.b16 {%0,%1,%2,%3}, [%4];"
                 : "=r"(r[0]), "=r"(r[1]), "=r"(r[2]), "=r"(r[3]) : "r"(a));
}
__device__ __forceinline__ void mma16816(float* c, const uint32_t* a,
                                         uint32_t b0, uint32_t b1) {
    asm volatile("mma.sync.aligned.m16n8k16.row.col.f32.f16.f16.f32 "
                 "{%0,%1,%2,%3}, {%4,%5,%6,%7}, {%8,%9}, {%0,%1,%2,%3};"
                 : "+f"(c[0]), "+f"(c[1]), "+f"(c[2]), "+f"(c[3])
                 : "r"(a[0]), "r"(a[1]), "r"(a[2]), "r"(a[3]), "r"(b0), "r"(b1));
}
#define CVTH2(res, hi, lo) \
    asm("cvt.rn.f16x2.f32 %0, %1, %2;" : "=r"(res) : "f"(hi), "f"(lo))

__device__ __forceinline__ float fexp(float x) {
    x = fmaxf(x, -80.f);
    float t = x * 1.44269504f;
    float fk = t + 12582912.f;
    int   i  = __float_as_int(fk) - 0x4B400000;
    float f  = t - (fk - 12582912.f);
    float p = 1.33978e-3f;
    p = fmaf(p, f, 9.67839e-3f);
    p = fmaf(p, f, 5.55041e-2f);
    p = fmaf(p, f, 2.40227e-1f);
    p = fmaf(p, f, 6.93147e-1f);
    p = fmaf(p, f, 1.0f);
    return __int_as_float(__float_as_int(p) + (i << 23));
}

// ---------------- prep ----------------
__global__ void conv_h(const float* __restrict__ in, __half* __restrict__ hi, int n4)
{
    int i = blockIdx.x * blockDim.x + threadIdx.x;
    if (i >= n4) return;
    float4 v = ((const float4*)in)[i];
    uint32_t h0, h1;
    CVTH2(h0, v.y, v.x);
    CVTH2(h1, v.w, v.z);
    ((uint32_t*)hi)[2 * i] = h0; ((uint32_t*)hi)[2 * i + 1] = h1;
}
__global__ void conv_wqkv(const float* __restrict__ wq, const float* __restrict__ wk,
                          const float* __restrict__ wv)
{
    int id = blockIdx.x * 256 + threadIdx.x;
    if (id >= 3 * Dm * Dm) return;
    int n = id >> 10, d = id & 1023;
    int proj = n >> 10, nl = n & 1023, h = nl >> 6, e = nl & 63;
    const float* W = (proj == 0 ? wq : proj == 1 ? wk : wv);
    g_wh[id] = __float2half_rn(W[((size_t)h * Dm + d) * Dh + e]);
}
__global__ void conv_wo(const float* __restrict__ wo)
{
    int id = blockIdx.x * 256 + threadIdx.x;
    if (id >= Dm * Dm) return;
    int n = id >> 10, k = id & 1023;
    g_oh[id] = __float2half_rn(wo[(size_t)k * Dm + n]);
}

// ---- fp16 single-pass HMMA GEMM: C = A*B^T + bias; 128x128, 2 CTA/SM -------
#define ARR_BYTES 8192
#define STG_BYTES (2 * ARR_BYTES)      /* A, B */
#define GEMM_SMEM (3 * STG_BYTES)      /* 49152 */

__global__ __launch_bounds__(256, 2) void hmma_gemm(
    const __half* __restrict__ A, const __half* __restrict__ B,
    const float* __restrict__ b0, const float* __restrict__ b1,
    const float* __restrict__ b2, float* __restrict__ C, int mode)
{
    extern __shared__ char smc[];
    const uint32_t sb = smem_u32(smc);
    const int tid = threadIdx.x, wid = tid >> 5, lane = tid & 31;
    const int warp_m = wid >> 2, warp_n = wid & 3;
    const int g = lane >> 3, r = lane & 7;
    const int m0  = blockIdx.x * 128;
    const int n0g = blockIdx.y * 128;
    const int proj = n0g >> 10;
    const int nl   = n0g & 1023;
    const float* bias = (proj == 0 ? b0 : proj == 1 ? b1 : b2);

    const __half* srcs[2];
    srcs[0] = A + (size_t)m0  * Dm;
    srcs[1] = B + (size_t)n0g * Dm;

    const uint32_t aoff0 = (uint32_t)(((warp_m * 8 + (g & 1)) * 4 + (g >> 1)) * 128 + r * 16);
    const uint32_t boff0 = (uint32_t)(((warp_n * 4 + (g >> 1)) * 4 + (g & 1)) * 128 + r * 16);

    auto fill = [&](int buf, int k0) {
        #pragma unroll
        for (int arr = 0; arr < 2; arr++) {
            uint32_t abase = sb + buf * STG_BYTES + arr * ARR_BYTES;
            const __half* s = srcs[arr];
            #pragma unroll
            for (int i = 0; i < 2; i++) {
                int cid = tid + 256 * i;
                int row = cid >> 2, kc = (cid & 3) * 8;
                CP_ASYNC16(abase + (uint32_t)(((row >> 3) * 4 + (kc >> 3)) * 128
                           + (row & 7) * 16),
                           s + (size_t)row * Dm + k0 + kc);
            }
        }
    };

    float acc[4][4][4];
    #pragma unroll
    for (int mi = 0; mi < 4; mi++)
        #pragma unroll
        for (int nj = 0; nj < 4; nj++)
            #pragma unroll
            for (int c = 0; c < 4; c++) acc[mi][nj][c] = 0.f;

    fill(0, 0);  CP_COMMIT();
    fill(1, 32); CP_COMMIT();

    const int NIT = Dm / 32;
    int buf = 0;
    for (int it = 0; it < NIT; it++) {
        if (it == NIT - 1) { CP_WAIT0(); } else { CP_WAIT1(); }
        __syncthreads();
        if (it + 2 < NIT) {
            int nb = buf + 2; if (nb >= 3) nb -= 3;
            fill(nb, (it + 2) * 32);
            CP_COMMIT();
        }

        const uint32_t stb = sb + buf * STG_BYTES;
        const uint32_t bA = stb, bB = stb + ARR_BYTES;

        #pragma unroll
        for (int ks = 0; ks < 2; ks++) {
            uint32_t afr[4][4];
            uint32_t bh[2][4];
            ldmat4(bh[0], bB + boff0 + ks * 256);
            ldmat4(bh[1], bB + boff0 + 1024 + ks * 256);
            #pragma unroll
            for (int mi = 0; mi < 4; mi++)
                ldmat4(afr[mi], bA + aoff0 + mi * 1024 + ks * 256);
            #pragma unroll
            for (int mi = 0; mi < 4; mi++)
                #pragma unroll
                for (int nj = 0; nj < 4; nj++)
                    mma16816(acc[mi][nj], afr[mi],
                             bh[nj >> 1][(nj & 1) * 2], bh[nj >> 1][(nj & 1) * 2 + 1]);
        }
        if (++buf >= 3) buf = 0;
    }

    const int gq = lane >> 2, tq = lane & 3;
    if (mode == 0) {
        #pragma unroll
        for (int mi = 0; mi < 4; mi++) {
            const int row = m0 + warp_m * 64 + mi * 16 + gq;
            #pragma unroll
            for (int nj = 0; nj < 4; nj++) {
                const int col = nl + warp_n * 32 + nj * 8 + tq * 2;
                const float bv0 = bias[col], bv1 = bias[col + 1];
                *(float2*)(C + (size_t)row * Dm + col) =
                    make_float2(acc[mi][nj][0] + bv0, acc[mi][nj][1] + bv1);
                *(float2*)(C + (size_t)(row + 8) * Dm + col) =
                    make_float2(acc[mi][nj][2] + bv0, acc[mi][nj][3] + bv1);
            }
        }
    } else {
        __half* H = (proj == 0 ? g_qh : proj == 1 ? g_kh : g_vh);
        const float sc = (proj == 0) ? 0.125f : 1.f;
        #pragma unroll
        for (int mi = 0; mi < 4; mi++) {
            const size_t row = (size_t)(m0 + warp_m * 64 + mi * 16 + gq);
            #pragma unroll
            for (int nj = 0; nj < 4; nj++) {
                const int col = nl + warp_n * 32 + nj * 8 + tq * 2;
                const float bv0 = bias[col], bv1 = bias[col + 1];
                uint32_t hv;
                CVTH2(hv, (acc[mi][nj][1] + bv1) * sc, (acc[mi][nj][0] + bv0) * sc);
                *(uint32_t*)(H + row * Dm + col) = hv;
                CVTH2(hv, (acc[mi][nj][3] + bv1) * sc, (acc[mi][nj][2] + bv0) * sc);
                *(uint32_t*)(H + (row + 8) * Dm + col) = hv;
            }
        }
    }
}

// ---------------- fp16 single-pass flash attention: KV tile 128 -------------
#define ATT_SMEM 65536
__device__ __forceinline__ uint32_t swo(int row, int e) {
    return (uint32_t)(((row >> 3) * 8 + (e >> 3)) * 128 + (((row & 7) ^ (e >> 3)) << 4));
}

__global__ __launch_bounds__(256) void fattn()
{
    extern __shared__ char sm[];
    const uint32_t sb = smem_u32(sm);
    const int tid = threadIdx.x, w = tid >> 5, lane = tid & 31;
    const int qb = gridDim.x - 1 - blockIdx.x;   // heavy tiles first
    const int h = blockIdx.y, b = blockIdx.z;
    const int q0 = qb * 128;
    const size_t tq0 = (size_t)b * Sq + q0;

    // stage Q (128x64 fp16 = 16KB) and pull into frags
    #pragma unroll
    for (int i = 0; i < 4; i++) {
        int sid = tid + 256 * i;
        int row = sid >> 3, c8 = sid & 7;
        CP_ASYNC16(sb + swo(row, c8 * 8),
                   g_qh + (tq0 + row) * Dm + h * 64 + c8 * 8);
    }
    CP_COMMIT(); CP_WAIT0(); __syncthreads();

    uint32_t qh[4][4];
    {
        int row = 16 * w + (lane & 7) + ((lane >> 3) & 1) * 8;
        #pragma unroll
        for (int ks = 0; ks < 4; ks++)
            ldmat4(qh[ks], sb + swo(row, ks * 16 + (lane >> 4) * 8));
    }
    __syncthreads();

    float o[8][4], m[2] = {-1e30f, -1e30f}, l[2] = {0.f, 0.f};
    #pragma unroll
    for (int nj = 0; nj < 8; nj++)
        #pragma unroll
        for (int c = 0; c < 4; c++) o[nj][c] = 0.f;

    const int nkv = qb + 1;
    const size_t tb = (size_t)b * Sq;

    auto fillkv = [&](int st, int kt) {
        #pragma unroll
        for (int i = 0; i < 8; i++) {
            int sid = tid + 256 * i;
            int arr = sid >> 10, rc = sid & 1023, row = rc >> 3, c8 = rc & 7;
            const __half* s = (arr == 0 ? g_kh : g_vh);
            CP_ASYNC16(sb + st * 32768 + arr * 16384 + swo(row, c8 * 8),
                       s + (tb + kt * 128 + row) * Dm + h * 64 + c8 * 8);
        }
    };

    fillkv(0, 0); CP_COMMIT();

    for (int kt = 0; kt < nkv; kt++) {
        CP_WAIT0();
        __syncthreads();
        if (kt + 1 < nkv) { fillkv((kt + 1) & 1, kt + 1); CP_COMMIT(); }

        const uint32_t kbb = sb + (kt & 1) * 32768;
        float s[16][4];
        #pragma unroll
        for (int nj = 0; nj < 16; nj++)
            #pragma unroll
            for (int c = 0; c < 4; c++) s[nj][c] = 0.f;

        // S = Q * K^T
        #pragma unroll
        for (int ks = 0; ks < 4; ks++) {
            #pragma unroll
            for (int njp = 0; njp < 8; njp++) {
                int krow = njp * 16 + (lane >> 4) * 8 + (lane & 7);
                uint32_t off = swo(krow, ks * 16 + ((lane >> 3) & 1) * 8);
                uint32_t kbh[4];
                ldmat4(kbh, kbb + off);
                mma16816(s[2 * njp],     qh[ks], kbh[0], kbh[1]);
                mma16816(s[2 * njp + 1], qh[ks], kbh[2], kbh[3]);
            }
        }

        if (kt == nkv - 1) {   // causal mask on diagonal tile
            const int rowA = q0 + 16 * w + (lane >> 2);
            #pragma unroll
            for (int nj = 0; nj < 16; nj++)
                #pragma unroll
                for (int c = 0; c < 4; c++) {
                    int col = kt * 128 + nj * 8 + (lane & 3) * 2 + (c & 1);
                    if (col > rowA + (c >> 1) * 8) s[nj][c] = -1e30f;
                }
        }

        float mxA = -1e30f, mxB = -1e30f;
        #pragma unroll
        for (int nj = 0; nj < 16; nj++) {
            mxA = fmaxf(mxA, fmaxf(s[nj][0], s[nj][1]));
            mxB = fmaxf(mxB, fmaxf(s[nj][2], s[nj][3]));
        }
        #pragma unroll
        for (int off = 1; off < 4; off <<= 1) {
            mxA = fmaxf(mxA, __shfl_xor_sync(0xffffffffu, mxA, off));
            mxB = fmaxf(mxB, __shfl_xor_sync(0xffffffffu, mxB, off));
        }
        float mA = fmaxf(m[0], mxA), mB = fmaxf(m[1], mxB);
        float scA = fexp(m[0] - mA), scB = fexp(m[1] - mB);
        m[0] = mA; m[1] = mB;
        float sA = 0.f, sB = 0.f;
        #pragma unroll
        for (int nj = 0; nj < 16; nj++) {
            s[nj][0] = fexp(s[nj][0] - mA); s[nj][1] = fexp(s[nj][1] - mA);
            s[nj][2] = fexp(s[nj][2] - mB); s[nj][3] = fexp(s[nj][3] - mB);
            sA += s[nj][0] + s[nj][1];
            sB += s[nj][2] + s[nj][3];
        }
        #pragma unroll
        for (int off = 1; off < 4; off <<= 1) {
            sA += __shfl_xor_sync(0xffffffffu, sA, off);
            sB += __shfl_xor_sync(0xffffffffu, sB, off);
        }
        l[0] = l[0] * scA + sA;
        l[1] = l[1] * scB + sB;
        #pragma unroll
        for (int nj = 0; nj < 8; nj++) {
            o[nj][0] *= scA; o[nj][1] *= scA; o[nj][2] *= scB; o[nj][3] *= scB;
        }

        // O += P * V
        const uint32_t vbb = kbb + 16384;
        #pragma unroll
        for (int kk = 0; kk < 8; kk++) {
            uint32_t pah[4];
            CVTH2(pah[0], s[2 * kk][1],     s[2 * kk][0]);
            CVTH2(pah[1], s[2 * kk][3],     s[2 * kk][2]);
            CVTH2(pah[2], s[2 * kk + 1][1], s[2 * kk + 1][0]);
            CVTH2(pah[3], s[2 * kk + 1][3], s[2 * kk + 1][2]);
            int vrow = kk * 16 + (lane & 7) + ((lane >> 3) & 1) * 8;
            #pragma unroll
            for (int ep = 0; ep < 4; ep++) {
                uint32_t off = swo(vrow, ep * 16 + (lane >> 4) * 8);
                uint32_t vbh[4];
                ldmat4t(vbh, vbb + off);
                mma16816(o[2 * ep],     pah, vbh[0], vbh[1]);
                mma16816(o[2 * ep + 1], pah, vbh[2], vbh[3]);
            }
        }
    }

    const float invA = 1.f / l[0], invB = 1.f / l[1];
    const size_t base = (tq0 + 16 * w + (lane >> 2)) * Dm + h * 64;
    #pragma unroll
    for (int nj = 0; nj < 8; nj++) {
        const int col = nj * 8 + (lane & 3) * 2;
        uint32_t p0, p1;
        CVTH2(p0, o[nj][1] * invA, o[nj][0] * invA);
        CVTH2(p1, o[nj][3] * invB, o[nj][2] * invB);
        *(uint32_t*)(g_zh + base + col)          = p0;
        *(uint32_t*)(g_zh + base + 8 * Dm + col) = p1;
    }
}

// ---------------------------------------------------------------------------
extern "C" void kernel_launch(void* const* d_in, const int* in_sizes, int n_in,
                              void* d_out, int out_size)
{
    const float* x  = (const float*)d_in[0];
    const float* wq = (const float*)d_in[1];
    const float* bq = (const float*)d_in[2];
    const float* wk = (const float*)d_in[3];
    const float* bk = (const float*)d_in[4];
    const float* wv = (const float*)d_in[5];
    const float* bv = (const float*)d_in[6];
    const float* wo = (const float*)d_in[7];
    const float* bo = (const float*)d_in[8];
    float* out = (float*)d_out;

    cudaFuncSetAttribute(hmma_gemm, cudaFuncAttributeMaxDynamicSharedMemorySize, GEMM_SMEM);
    cudaFuncSetAttribute(fattn,     cudaFuncAttributeMaxDynamicSharedMemorySize, ATT_SMEM);

    void* p;
    cudaGetSymbolAddress(&p, g_xh); __half* xh = (__half*)p;
    cudaGetSymbolAddress(&p, g_zh); __half* zh = (__half*)p;
    cudaGetSymbolAddress(&p, g_wh); __half* wh = (__half*)p;
    cudaGetSymbolAddress(&p, g_oh); __half* oh = (__half*)p;

    conv_h<<<(Tt * Dm / 4 + 255) / 256, 256>>>(x, xh, Tt * Dm / 4);
    conv_wqkv<<<(3 * Dm * Dm + 255) / 256, 256>>>(wq, wk, wv);
    conv_wo<<<(Dm * Dm + 255) / 256, 256>>>(wo);

    // QKV projection -> Q (fp16, x0.125), K, V (fp16)
    hmma_gemm<<<dim3(Tt / 128, 24), 256, GEMM_SMEM>>>(
        xh, wh, bq, bk, bv, nullptr, 1);

    // flash attention -> z (fp16)
    fattn<<<dim3(Sq / 128, Hh, Bsz), 256, ATT_SMEM>>>();

    // output projection -> fp32 out
    hmma_gemm<<<dim3(Tt / 128, 8), 256, GEMM_SMEM>>>(
        zh, oh, bo, bo, bo, out, 0);
}

// round 12
// speedup vs baseline: 2.2848x; 1.0647x over previous
#include <cuda_runtime.h>
#include <cuda_fp16.h>
#include <cstdint>

#define Bsz 4
#define Sq  2048
#define Dm  1024
#define Hh  16
#define Dh  64
#define Tt  (Bsz * Sq)

// ---------------- scratch (all single fp16) ----------------
__device__ __half g_xh[(size_t)Tt * Dm];
__device__ __half g_wh[(size_t)3 * Dm * Dm];
__device__ __half g_oh[(size_t)Dm * Dm];
__device__ __half g_qh[(size_t)Tt * Dm];
__device__ __half g_kh[(size_t)Tt * Dm];
__device__ __half g_vh[(size_t)Tt * Dm];
__device__ __half g_zh[(size_t)Tt * Dm];

// ---------------- helpers (arch-stable PTX only) ----------------
__device__ __forceinline__ uint32_t smem_u32(const void* p) {
    uint32_t a;
    asm("{ .reg .u64 t; cvta.to.shared.u64 t, %1; cvt.u32.u64 %0, t; }" : "=r"(a) : "l"(p));
    return a;
}
#define CP_ASYNC16(dst, src) \
    asm volatile("cp.async.cg.shared.global [%0], [%1], 16;" :: "r"(dst), "l"(src))
#define CP_COMMIT() asm volatile("cp.async.commit_group;" ::: "memory")
#define CP_WAIT1()  asm volatile("cp.async.wait_group 1;" ::: "memory")
#define CP_WAIT0()  asm volatile("cp.async.wait_group 0;" ::: "memory")

__device__ __forceinline__ void ldmat4(uint32_t r[4], uint32_t a) {
    asm volatile("ldmatrix.sync.aligned.m8n8.x4.shared.b16 {%0,%1,%2,%3}, [%4];"
                 : "=r"(r[0]), "=r"(r[1]), "=r"(r[2]), "=r"(r[3]) : "r"(a));
}
__device__ __forceinline__ void ldmat4t(uint32_t r[4], uint32_t a) {
    asm volatile("ldmatrix.sync.aligned.m8n8.x4.trans.shared.b16 {%0,%1,%2,%3}, [%4];"
                 : "=r"(r[0]), "=r"(r[1]), "=r"(r[2]), "=r"(r[3]) : "r"(a));
}
__device__ __forceinline__ void mma16816(float* c, const uint32_t* a,
                                         uint32_t b0, uint32_t b1) {
    asm volatile("mma.sync.aligned.m16n8k16.row.col.f32.f16.f16.f32 "
                 "{%0,%1,%2,%3}, {%4,%5,%6,%7}, {%8,%9}, {%0,%1,%2,%3};"
                 : "+f"(c[0]), "+f"(c[1]), "+f"(c[2]), "+f"(c[3])
                 : "r"(a[0]), "r"(a[1]), "r"(a[2]), "r"(a[3]), "r"(b0), "r"(b1));
}
#define CVTH2(res, hi, lo) \
    asm("cvt.rn.f16x2.f32 %0, %1, %2;" : "=r"(res) : "f"(hi), "f"(lo))

__device__ __forceinline__ float fexp(float x) {
    x = fmaxf(x, -80.f);
    float t = x * 1.44269504f;
    float fk = t + 12582912.f;
    int   i  = __float_as_int(fk) - 0x4B400000;
    float f  = t - (fk - 12582912.f);
    float p = 1.33978e-3f;
    p = fmaf(p, f, 9.67839e-3f);
    p = fmaf(p, f, 5.55041e-2f);
    p = fmaf(p, f, 2.40227e-1f);
    p = fmaf(p, f, 6.93147e-1f);
    p = fmaf(p, f, 1.0f);
    return __int_as_float(__float_as_int(p) + (i << 23));
}

// ---------------- prep ----------------
__global__ void conv_h(const float* __restrict__ in, __half* __restrict__ hi, int n4)
{
    int i = blockIdx.x * blockDim.x + threadIdx.x;
    if (i >= n4) return;
    float4 v = ((const float4*)in)[i];
    uint32_t h0, h1;
    CVTH2(h0, v.y, v.x);
    CVTH2(h1, v.w, v.z);
    ((uint32_t*)hi)[2 * i] = h0; ((uint32_t*)hi)[2 * i + 1] = h1;
}
__global__ void conv_wqkv(const float* __restrict__ wq, const float* __restrict__ wk,
                          const float* __restrict__ wv)
{
    int id = blockIdx.x * 256 + threadIdx.x;
    if (id >= 3 * Dm * Dm) return;
    int n = id >> 10, d = id & 1023;
    int proj = n >> 10, nl = n & 1023, h = nl >> 6, e = nl & 63;
    const float* W = (proj == 0 ? wq : proj == 1 ? wk : wv);
    g_wh[id] = __float2half_rn(W[((size_t)h * Dm + d) * Dh + e]);
}
__global__ void conv_wo(const float* __restrict__ wo)
{
    int id = blockIdx.x * 256 + threadIdx.x;
    if (id >= Dm * Dm) return;
    int n = id >> 10, k = id & 1023;
    g_oh[id] = __float2half_rn(wo[(size_t)k * Dm + n]);
}

// ---- fp16 HMMA GEMM: CTA 128x128, 4 warps (2x2), warp tile 64x64 -----------
// 64 FLOP/smem-byte; 2 CTAs/SM via launch_bounds(128,2).
#define ARR_BYTES 8192
#define STG_BYTES (2 * ARR_BYTES)      /* A, B */
#define GEMM_SMEM (3 * STG_BYTES)      /* 49152 */

__global__ __launch_bounds__(128, 2) void hmma_gemm(
    const __half* __restrict__ A, const __half* __restrict__ B,
    const float* __restrict__ b0, const float* __restrict__ b1,
    const float* __restrict__ b2, float* __restrict__ C, int mode)
{
    extern __shared__ char smc[];
    const uint32_t sb = smem_u32(smc);
    const int tid = threadIdx.x, wid = tid >> 5, lane = tid & 31;
    const int warp_m = wid >> 1, warp_n = wid & 1;
    const int g = lane >> 3, r = lane & 7;
    const int m0  = blockIdx.x * 128;
    const int n0g = blockIdx.y * 128;
    const int proj = n0g >> 10;
    const int nl   = n0g & 1023;
    const float* bias = (proj == 0 ? b0 : proj == 1 ? b1 : b2);

    const __half* srcs[2];
    srcs[0] = A + (size_t)m0  * Dm;
    srcs[1] = B + (size_t)n0g * Dm;

    const uint32_t aoff0 = (uint32_t)(((warp_m * 8 + (g & 1)) * 4 + (g >> 1)) * 128 + r * 16);
    const uint32_t boff0 = (uint32_t)(((warp_n * 8 + (g >> 1)) * 4 + (g & 1)) * 128 + r * 16);

    auto fill = [&](int buf, int k0) {
        #pragma unroll
        for (int arr = 0; arr < 2; arr++) {
            uint32_t abase = sb + buf * STG_BYTES + arr * ARR_BYTES;
            const __half* s = srcs[arr];
            #pragma unroll
            for (int i = 0; i < 4; i++) {
                int cid = tid + 128 * i;
                int row = cid >> 2, kc = (cid & 3) * 8;
                CP_ASYNC16(abase + (uint32_t)(((row >> 3) * 4 + (kc >> 3)) * 128
                           + (row & 7) * 16),
                           s + (size_t)row * Dm + k0 + kc);
            }
        }
    };

    float acc[4][8][4];
    #pragma unroll
    for (int mi = 0; mi < 4; mi++)
        #pragma unroll
        for (int nj = 0; nj < 8; nj++)
            #pragma unroll
            for (int c = 0; c < 4; c++) acc[mi][nj][c] = 0.f;

    fill(0, 0);  CP_COMMIT();
    fill(1, 32); CP_COMMIT();

    const int NIT = Dm / 32;
    int buf = 0;
    for (int it = 0; it < NIT; it++) {
        if (it == NIT - 1) { CP_WAIT0(); } else { CP_WAIT1(); }
        __syncthreads();
        if (it + 2 < NIT) {
            int nb = buf + 2; if (nb >= 3) nb -= 3;
            fill(nb, (it + 2) * 32);
            CP_COMMIT();
        }

        const uint32_t stb = sb + buf * STG_BYTES;
        const uint32_t bA = stb, bB = stb + ARR_BYTES;

        #pragma unroll
        for (int ks = 0; ks < 2; ks++) {
            uint32_t afr[4][4];
            #pragma unroll
            for (int mi = 0; mi < 4; mi++)
                ldmat4(afr[mi], bA + aoff0 + mi * 1024 + ks * 256);
            #pragma unroll
            for (int np = 0; np < 4; np++) {
                uint32_t bb[4];
                ldmat4(bb, bB + boff0 + np * 1024 + ks * 256);
                #pragma unroll
                for (int mi = 0; mi < 4; mi++) {
                    mma16816(acc[mi][2 * np],     afr[mi], bb[0], bb[1]);
                    mma16816(acc[mi][2 * np + 1], afr[mi], bb[2], bb[3]);
                }
            }
        }
        if (++buf >= 3) buf = 0;
    }

    const int gq = lane >> 2, tq = lane & 3;
    if (mode == 0) {
        #pragma unroll
        for (int mi = 0; mi < 4; mi++) {
            const int row = m0 + warp_m * 64 + mi * 16 + gq;
            #pragma unroll
            for (int nj = 0; nj < 8; nj++) {
                const int col = nl + warp_n * 64 + nj * 8 + tq * 2;
                const float bv0 = bias[col], bv1 = bias[col + 1];
                *(float2*)(C + (size_t)row * Dm + col) =
                    make_float2(acc[mi][nj][0] + bv0, acc[mi][nj][1] + bv1);
                *(float2*)(C + (size_t)(row + 8) * Dm + col) =
                    make_float2(acc[mi][nj][2] + bv0, acc[mi][nj][3] + bv1);
            }
        }
    } else {
        __half* H = (proj == 0 ? g_qh : proj == 1 ? g_kh : g_vh);
        const float sc = (proj == 0) ? 0.125f : 1.f;
        #pragma unroll
        for (int mi = 0; mi < 4; mi++) {
            const size_t row = (size_t)(m0 + warp_m * 64 + mi * 16 + gq);
            #pragma unroll
            for (int nj = 0; nj < 8; nj++) {
                const int col = nl + warp_n * 64 + nj * 8 + tq * 2;
                const float bv0 = bias[col], bv1 = bias[col + 1];
                uint32_t hv;
                CVTH2(hv, (acc[mi][nj][1] + bv1) * sc, (acc[mi][nj][0] + bv0) * sc);
                *(uint32_t*)(H + row * Dm + col) = hv;
                CVTH2(hv, (acc[mi][nj][3] + bv1) * sc, (acc[mi][nj][2] + bv0) * sc);
                *(uint32_t*)(H + (row + 8) * Dm + col) = hv;
            }
        }
    }
}

// ---------------- fp16 single-pass flash attention (unchanged R11) ----------
#define ATT_SMEM 65536
__device__ __forceinline__ uint32_t swo(int row, int e) {
    return (uint32_t)(((row >> 3) * 8 + (e >> 3)) * 128 + (((row & 7) ^ (e >> 3)) << 4));
}

__global__ __launch_bounds__(256) void fattn()
{
    extern __shared__ char sm[];
    const uint32_t sb = smem_u32(sm);
    const int tid = threadIdx.x, w = tid >> 5, lane = tid & 31;
    const int qb = gridDim.x - 1 - blockIdx.x;   // heavy tiles first
    const int h = blockIdx.y, b = blockIdx.z;
    const int q0 = qb * 128;
    const size_t tq0 = (size_t)b * Sq + q0;

    #pragma unroll
    for (int i = 0; i < 4; i++) {
        int sid = tid + 256 * i;
        int row = sid >> 3, c8 = sid & 7;
        CP_ASYNC16(sb + swo(row, c8 * 8),
                   g_qh + (tq0 + row) * Dm + h * 64 + c8 * 8);
    }
    CP_COMMIT(); CP_WAIT0(); __syncthreads();

    uint32_t qh[4][4];
    {
        int row = 16 * w + (lane & 7) + ((lane >> 3) & 1) * 8;
        #pragma unroll
        for (int ks = 0; ks < 4; ks++)
            ldmat4(qh[ks], sb + swo(row, ks * 16 + (lane >> 4) * 8));
    }
    __syncthreads();

    float o[8][4], m[2] = {-1e30f, -1e30f}, l[2] = {0.f, 0.f};
    #pragma unroll
    for (int nj = 0; nj < 8; nj++)
        #pragma unroll
        for (int c = 0; c < 4; c++) o[nj][c] = 0.f;

    const int nkv = qb + 1;
    const size_t tb = (size_t)b * Sq;

    auto fillkv = [&](int st, int kt) {
        #pragma unroll
        for (int i = 0; i < 8; i++) {
            int sid = tid + 256 * i;
            int arr = sid >> 10, rc = sid & 1023, row = rc >> 3, c8 = rc & 7;
            const __half* s = (arr == 0 ? g_kh : g_vh);
            CP_ASYNC16(sb + st * 32768 + arr * 16384 + swo(row, c8 * 8),
                       s + (tb + kt * 128 + row) * Dm + h * 64 + c8 * 8);
        }
    };

    fillkv(0, 0); CP_COMMIT();

    for (int kt = 0; kt < nkv; kt++) {
        CP_WAIT0();
        __syncthreads();
        if (kt + 1 < nkv) { fillkv((kt + 1) & 1, kt + 1); CP_COMMIT(); }

        const uint32_t kbb = sb + (kt & 1) * 32768;
        float s[16][4];
        #pragma unroll
        for (int nj = 0; nj < 16; nj++)
            #pragma unroll
            for (int c = 0; c < 4; c++) s[nj][c] = 0.f;

        #pragma unroll
        for (int ks = 0; ks < 4; ks++) {
            #pragma unroll
            for (int njp = 0; njp < 8; njp++) {
                int krow = njp * 16 + (lane >> 4) * 8 + (lane & 7);
                uint32_t off = swo(krow, ks * 16 + ((lane >> 3) & 1) * 8);
                uint32_t kbh[4];
                ldmat4(kbh, kbb + off);
                mma16816(s[2 * njp],     qh[ks], kbh[0], kbh[1]);
                mma16816(s[2 * njp + 1], qh[ks], kbh[2], kbh[3]);
            }
        }

        if (kt == nkv - 1) {
            const int rowA = q0 + 16 * w + (lane >> 2);
            #pragma unroll
            for (int nj = 0; nj < 16; nj++)
                #pragma unroll
                for (int c = 0; c < 4; c++) {
                    int col = kt * 128 + nj * 8 + (lane & 3) * 2 + (c & 1);
                    if (col > rowA + (c >> 1) * 8) s[nj][c] = -1e30f;
                }
        }

        float mxA = -1e30f, mxB = -1e30f;
        #pragma unroll
        for (int nj = 0; nj < 16; nj++) {
            mxA = fmaxf(mxA, fmaxf(s[nj][0], s[nj][1]));
            mxB = fmaxf(mxB, fmaxf(s[nj][2], s[nj][3]));
        }
        #pragma unroll
        for (int off = 1; off < 4; off <<= 1) {
            mxA = fmaxf(mxA, __shfl_xor_sync(0xffffffffu, mxA, off));
            mxB = fmaxf(mxB, __shfl_xor_sync(0xffffffffu, mxB, off));
        }
        float mA = fmaxf(m[0], mxA), mB = fmaxf(m[1], mxB);
        float scA = fexp(m[0] - mA), scB = fexp(m[1] - mB);
        m[0] = mA; m[1] = mB;
        float sA = 0.f, sB = 0.f;
        #pragma unroll
        for (int nj = 0; nj < 16; nj++) {
            s[nj][0] = fexp(s[nj][0] - mA); s[nj][1] = fexp(s[nj][1] - mA);
            s[nj][2] = fexp(s[nj][2] - mB); s[nj][3] = fexp(s[nj][3] - mB);
            sA += s[nj][0] + s[nj][1];
            sB += s[nj][2] + s[nj][3];
        }
        #pragma unroll
        for (int off = 1; off < 4; off <<= 1) {
            sA += __shfl_xor_sync(0xffffffffu, sA, off);
            sB += __shfl_xor_sync(0xffffffffu, sB, off);
        }
        l[0] = l[0] * scA + sA;
        l[1] = l[1] * scB + sB;
        #pragma unroll
        for (int nj = 0; nj < 8; nj++) {
            o[nj][0] *= scA; o[nj][1] *= scA; o[nj][2] *= scB; o[nj][3] *= scB;
        }

        const uint32_t vbb = kbb + 16384;
        #pragma unroll
        for (int kk = 0; kk < 8; kk++) {
            uint32_t pah[4];
            CVTH2(pah[0], s[2 * kk][1],     s[2 * kk][0]);
            CVTH2(pah[1], s[2 * kk][3],     s[2 * kk][2]);
            CVTH2(pah[2], s[2 * kk + 1][1], s[2 * kk + 1][0]);
            CVTH2(pah[3], s[2 * kk + 1][3], s[2 * kk + 1][2]);
            int vrow = kk * 16 + (lane & 7) + ((lane >> 3) & 1) * 8;
            #pragma unroll
            for (int ep = 0; ep < 4; ep++) {
                uint32_t off = swo(vrow, ep * 16 + (lane >> 4) * 8);
                uint32_t vbh[4];
                ldmat4t(vbh, vbb + off);
                mma16816(o[2 * ep],     pah, vbh[0], vbh[1]);
                mma16816(o[2 * ep + 1], pah, vbh[2], vbh[3]);
            }
        }
    }

    const float invA = 1.f / l[0], invB = 1.f / l[1];
    const size_t base = (tq0 + 16 * w + (lane >> 2)) * Dm + h * 64;
    #pragma unroll
    for (int nj = 0; nj < 8; nj++) {
        const int col = nj * 8 + (lane & 3) * 2;
        uint32_t p0, p1;
        CVTH2(p0, o[nj][1] * invA, o[nj][0] * invA);
        CVTH2(p1, o[nj][3] * invB, o[nj][2] * invB);
        *(uint32_t*)(g_zh + base + col)          = p0;
        *(uint32_t*)(g_zh + base + 8 * Dm + col) = p1;
    }
}

// ---------------------------------------------------------------------------
extern "C" void kernel_launch(void* const* d_in, const int* in_sizes, int n_in,
                              void* d_out, int out_size)
{
    const float* x  = (const float*)d_in[0];
    const float* wq = (const float*)d_in[1];
    const float* bq = (const float*)d_in[2];
    const float* wk = (const float*)d_in[3];
    const float* bk = (const float*)d_in[4];
    const float* wv = (const float*)d_in[5];
    const float* bv = (const float*)d_in[6];
    const float* wo = (const float*)d_in[7];
    const float* bo = (const float*)d_in[8];
    float* out = (float*)d_out;

    cudaFuncSetAttribute(hmma_gemm, cudaFuncAttributeMaxDynamicSharedMemorySize, GEMM_SMEM);
    cudaFuncSetAttribute(fattn,     cudaFuncAttributeMaxDynamicSharedMemorySize, ATT_SMEM);

    void* p;
    cudaGetSymbolAddress(&p, g_xh); __half* xh = (__half*)p;
    cudaGetSymbolAddress(&p, g_zh); __half* zh = (__half*)p;
    cudaGetSymbolAddress(&p, g_wh); __half* wh = (__half*)p;
    cudaGetSymbolAddress(&p, g_oh); __half* oh = (__half*)p;

    conv_h<<<(Tt * Dm / 4 + 255) / 256, 256>>>(x, xh, Tt * Dm / 4);
    conv_wqkv<<<(3 * Dm * Dm + 255) / 256, 256>>>(wq, wk, wv);
    conv_wo<<<(Dm * Dm + 255) / 256, 256>>>(wo);

    hmma_gemm<<<dim3(Tt / 128, 24), 128, GEMM_SMEM>>>(
        xh, wh, bq, bk, bv, nullptr, 1);

    fattn<<<dim3(Sq / 128, Hh, Bsz), 256, ATT_SMEM>>>();

    hmma_gemm<<<dim3(Tt / 128, 8), 128, GEMM_SMEM>>>(
        zh, oh, bo, bo, bo, out, 0);
}

// round 14
// speedup vs baseline: 2.3123x; 1.0121x over previous
#include <cuda_runtime.h>
#include <cuda_fp16.h>
#include <cstdint>

#define Bsz 4
#define Sq  2048
#define Dm  1024
#define Hh  16
#define Dh  64
#define Tt  (Bsz * Sq)

// ---------------- scratch (all single fp16) ----------------
__device__ __half g_xh[(size_t)Tt * Dm];
__device__ __half g_wh[(size_t)3 * Dm * Dm];
__device__ __half g_oh[(size_t)Dm * Dm];
__device__ __half g_qh[(size_t)Tt * Dm];   // Q scaled by 0.125*log2(e)
__device__ __half g_kh[(size_t)Tt * Dm];
__device__ __half g_vh[(size_t)Tt * Dm];
__device__ __half g_zh[(size_t)Tt * Dm];

// ---------------- helpers (arch-stable PTX only) ----------------
__device__ __forceinline__ uint32_t smem_u32(const void* p) {
    uint32_t a;
    asm("{ .reg .u64 t; cvta.to.shared.u64 t, %1; cvt.u32.u64 %0, t; }" : "=r"(a) : "l"(p));
    return a;
}
#define CP_ASYNC16(dst, src) \
    asm volatile("cp.async.cg.shared.global [%0], [%1], 16;" :: "r"(dst), "l"(src))
#define CP_COMMIT() asm volatile("cp.async.commit_group;" ::: "memory")
#define CP_WAIT1()  asm volatile("cp.async.wait_group 1;" ::: "memory")
#define CP_WAIT0()  asm volatile("cp.async.wait_group 0;" ::: "memory")

__device__ __forceinline__ void ldmat4(uint32_t r[4], uint32_t a) {
    asm volatile("ldmatrix.sync.aligned.m8n8.x4.shared.b16 {%0,%1,%2,%3}, [%4];"
                 : "=r"(r[0]), "=r"(r[1]), "=r"(r[2]), "=r"(r[3]) : "r"(a));
}
__device__ __forceinline__ void ldmat4t(uint32_t r[4], uint32_t a) {
    asm volatile("ldmatrix.sync.aligned.m8n8.x4.trans.shared.b16 {%0,%1,%2,%3}, [%4];"
                 : "=r"(r[0]), "=r"(r[1]), "=r"(r[2]), "=r"(r[3]) : "r"(a));
}
__device__ __forceinline__ void mma16816(float* c, const uint32_t* a,
                                         uint32_t b0, uint32_t b1) {
    asm volatile("mma.sync.aligned.m16n8k16.row.col.f32.f16.f16.f32 "
                 "{%0,%1,%2,%3}, {%4,%5,%6,%7}, {%8,%9}, {%0,%1,%2,%3};"
                 : "+f"(c[0]), "+f"(c[1]), "+f"(c[2]), "+f"(c[3])
                 : "r"(a[0]), "r"(a[1]), "r"(a[2]), "r"(a[3]), "r"(b0), "r"(b1));
}
#define CVTH2(res, hi, lo) \
    asm("cvt.rn.f16x2.f32 %0, %1, %2;" : "=r"(res) : "f"(hi), "f"(lo))

// exp2 on fma/alu pipes (input in log2 domain, x <= 0)
__device__ __forceinline__ float fexp2(float x) {
    x = fmaxf(x, -100.f);
    float fk = x + 12582912.f;
    int   i  = __float_as_int(fk) - 0x4B400000;
    float f  = x - (fk - 12582912.f);
    float p = 1.33978e-3f;
    p = fmaf(p, f, 9.67839e-3f);
    p = fmaf(p, f, 5.55041e-2f);
    p = fmaf(p, f, 2.40227e-1f);
    p = fmaf(p, f, 6.93147e-1f);
    p = fmaf(p, f, 1.0f);
    return __int_as_float(__float_as_int(p) + (i << 23));
}

// ---------------- prep ----------------
__global__ void conv_h(const float* __restrict__ in, __half* __restrict__ hi, int n4)
{
    int i = blockIdx.x * blockDim.x + threadIdx.x;
    if (i >= n4) return;
    float4 v = ((const float4*)in)[i];
    uint32_t h0, h1;
    CVTH2(h0, v.y, v.x);
    CVTH2(h1, v.w, v.z);
    ((uint32_t*)hi)[2 * i] = h0; ((uint32_t*)hi)[2 * i + 1] = h1;
}
__global__ void conv_wqkv(const float* __restrict__ wq, const float* __restrict__ wk,
                          const float* __restrict__ wv)
{
    int id = blockIdx.x * 256 + threadIdx.x;
    if (id >= 3 * Dm * Dm) return;
    int n = id >> 10, d = id & 1023;
    int proj = n >> 10, nl = n & 1023, h = nl >> 6, e = nl & 63;
    const float* W = (proj == 0 ? wq : proj == 1 ? wk : wv);
    g_wh[id] = __float2half_rn(W[((size_t)h * Dm + d) * Dh + e]);
}
__global__ void conv_wo(const float* __restrict__ wo)
{
    int id = blockIdx.x * 256 + threadIdx.x;
    if (id >= Dm * Dm) return;
    int n = id >> 10, k = id & 1023;
    g_oh[id] = __float2half_rn(wo[(size_t)k * Dm + n]);
}

// ---- fp16 HMMA GEMM: CTA 128x128, 4 warps (2x2), warp tile 64x64 -----------
#define ARR_BYTES 8192
#define STG_BYTES (2 * ARR_BYTES)
#define GEMM_SMEM (3 * STG_BYTES)      /* 49152 */

__global__ __launch_bounds__(128, 2) void hmma_gemm(
    const __half* __restrict__ A, const __half* __restrict__ B,
    const float* __restrict__ b0, const float* __restrict__ b1,
    const float* __restrict__ b2, float* __restrict__ C, int mode)
{
    extern __shared__ char smc[];
    const uint32_t sb = smem_u32(smc);
    const int tid = threadIdx.x, wid = tid >> 5, lane = tid & 31;
    const int warp_m = wid >> 1, warp_n = wid & 1;
    const int g = lane >> 3, r = lane & 7;
    const int m0  = blockIdx.x * 128;
    const int n0g = blockIdx.y * 128;
    const int proj = n0g >> 10;
    const int nl   = n0g & 1023;
    const float* bias = (proj == 0 ? b0 : proj == 1 ? b1 : b2);

    const __half* srcs[2];
    srcs[0] = A + (size_t)m0  * Dm;
    srcs[1] = B + (size_t)n0g * Dm;

    const uint32_t aoff0 = (uint32_t)(((warp_m * 8 + (g & 1)) * 4 + (g >> 1)) * 128 + r * 16);
    const uint32_t boff0 = (uint32_t)(((warp_n * 8 + (g >> 1)) * 4 + (g & 1)) * 128 + r * 16);

    auto fill = [&](int buf, int k0) {
        #pragma unroll
        for (int arr = 0; arr < 2; arr++) {
            uint32_t abase = sb + buf * STG_BYTES + arr * ARR_BYTES;
            const __half* s = srcs[arr];
            #pragma unroll
            for (int i = 0; i < 4; i++) {
                int cid = tid + 128 * i;
                int row = cid >> 2, kc = (cid & 3) * 8;
                CP_ASYNC16(abase + (uint32_t)(((row >> 3) * 4 + (kc >> 3)) * 128
                           + (row & 7) * 16),
                           s + (size_t)row * Dm + k0 + kc);
            }
        }
    };

    float acc[4][8][4];
    #pragma unroll
    for (int mi = 0; mi < 4; mi++)
        #pragma unroll
        for (int nj = 0; nj < 8; nj++)
            #pragma unroll
            for (int c = 0; c < 4; c++) acc[mi][nj][c] = 0.f;

    fill(0, 0);  CP_COMMIT();
    fill(1, 32); CP_COMMIT();

    const int NIT = Dm / 32;
    int buf = 0;
    for (int it = 0; it < NIT; it++) {
        if (it == NIT - 1) { CP_WAIT0(); } else { CP_WAIT1(); }
        __syncthreads();
        if (it + 2 < NIT) {
            int nb = buf + 2; if (nb >= 3) nb -= 3;
            fill(nb, (it + 2) * 32);
            CP_COMMIT();
        }

        const uint32_t stb = sb + buf * STG_BYTES;
        const uint32_t bA = stb, bB = stb + ARR_BYTES;

        #pragma unroll
        for (int ks = 0; ks < 2; ks++) {
            uint32_t afr[4][4];
            #pragma unroll
            for (int mi = 0; mi < 4; mi++)
                ldmat4(afr[mi], bA + aoff0 + mi * 1024 + ks * 256);
            #pragma unroll
            for (int np = 0; np < 4; np++) {
                uint32_t bb[4];
                ldmat4(bb, bB + boff0 + np * 1024 + ks * 256);
                #pragma unroll
                for (int mi = 0; mi < 4; mi++) {
                    mma16816(acc[mi][2 * np],     afr[mi], bb[0], bb[1]);
                    mma16816(acc[mi][2 * np + 1], afr[mi], bb[2], bb[3]);
                }
            }
        }
        if (++buf >= 3) buf = 0;
    }

    const int gq = lane >> 2, tq = lane & 3;
    if (mode == 0) {
        #pragma unroll
        for (int mi = 0; mi < 4; mi++) {
            const int row = m0 + warp_m * 64 + mi * 16 + gq;
            #pragma unroll
            for (int nj = 0; nj < 8; nj++) {
                const int col = nl + warp_n * 64 + nj * 8 + tq * 2;
                const float bv0 = bias[col], bv1 = bias[col + 1];
                *(float2*)(C + (size_t)row * Dm + col) =
                    make_float2(acc[mi][nj][0] + bv0, acc[mi][nj][1] + bv1);
                *(float2*)(C + (size_t)(row + 8) * Dm + col) =
                    make_float2(acc[mi][nj][2] + bv0, acc[mi][nj][3] + bv1);
            }
        }
    } else {
        __half* H = (proj == 0 ? g_qh : proj == 1 ? g_kh : g_vh);
        const float sc = (proj == 0) ? 0.125f * 1.44269504f : 1.f;  // fold log2e into Q
        #pragma unroll
        for (int mi = 0; mi < 4; mi++) {
            const size_t row = (size_t)(m0 + warp_m * 64 + mi * 16 + gq);
            #pragma unroll
            for (int nj = 0; nj < 8; nj++) {
                const int col = nl + warp_n * 64 + nj * 8 + tq * 2;
                const float bv0 = bias[col], bv1 = bias[col + 1];
                uint32_t hv;
                CVTH2(hv, (acc[mi][nj][1] + bv1) * sc, (acc[mi][nj][0] + bv0) * sc);
                *(uint32_t*)(H + row * Dm + col) = hv;
                CVTH2(hv, (acc[mi][nj][3] + bv1) * sc, (acc[mi][nj][2] + bv0) * sc);
                *(uint32_t*)(H + (row + 8) * Dm + col) = hv;
            }
        }
    }
}

// ---- fp16 flash attention: KV tile 64, 2 CTAs/SM, scores in log2 domain ----
#define ATT_SMEM 32768     /* 2 stages x (K 8KB + V 8KB) */
__device__ __forceinline__ uint32_t swo(int row, int e) {
    return (uint32_t)(((row >> 3) * 8 + (e >> 3)) * 128 + (((row & 7) ^ (e >> 3)) << 4));
}

__global__ __launch_bounds__(256, 2) void fattn()
{
    extern __shared__ char sm[];
    const uint32_t sb = smem_u32(sm);
    const int tid = threadIdx.x, w = tid >> 5, lane = tid & 31;
    const int qb = gridDim.x - 1 - blockIdx.x;   // heavy tiles first
    const int h = blockIdx.y, b = blockIdx.z;
    const int q0 = qb * 128;
    const size_t tq0 = (size_t)b * Sq + q0;

    // stage Q (128x64 fp16 = 16KB, overlaps kv buffers pre-loop) -> frags
    #pragma unroll
    for (int i = 0; i < 4; i++) {
        int sid = tid + 256 * i;
        int row = sid >> 3, c8 = sid & 7;
        CP_ASYNC16(sb + swo(row, c8 * 8),
                   g_qh + (tq0 + row) * Dm + h * 64 + c8 * 8);
    }
    CP_COMMIT(); CP_WAIT0(); __syncthreads();

    uint32_t qh[4][4];
    {
        int row = 16 * w + (lane & 7) + ((lane >> 3) & 1) * 8;
        #pragma unroll
        for (int ks = 0; ks < 4; ks++)
            ldmat4(qh[ks], sb + swo(row, ks * 16 + (lane >> 4) * 8));
    }
    __syncthreads();

    float o[8][4], m[2] = {-1e30f, -1e30f}, l[2] = {0.f, 0.f};
    #pragma unroll
    for (int nj = 0; nj < 8; nj++)
        #pragma unroll
        for (int c = 0; c < 4; c++) o[nj][c] = 0.f;

    const int nkv = 2 * qb + 2;
    const size_t tb = (size_t)b * Sq;

    auto fillkv = [&](int st, int kt) {
        #pragma unroll
        for (int i = 0; i < 4; i++) {
            int sid = tid + 256 * i;
            int arr = sid >> 9, rc = sid & 511, row = rc >> 3, c8 = rc & 7;
            const __half* s = (arr == 0 ? g_kh : g_vh);
            CP_ASYNC16(sb + st * 16384 + arr * 8192 + swo(row, c8 * 8),
                       s + (tb + kt * 64 + row) * Dm + h * 64 + c8 * 8);
        }
    };

    fillkv(0, 0); CP_COMMIT();

    for (int kt = 0; kt < nkv; kt++) {
        CP_WAIT0();
        __syncthreads();
        if (kt + 1 < nkv) { fillkv((kt + 1) & 1, kt + 1); CP_COMMIT(); }

        const uint32_t kbb = sb + (kt & 1) * 16384;
        float s[8][4];
        #pragma unroll
        for (int nj = 0; nj < 8; nj++)
            #pragma unroll
            for (int c = 0; c < 4; c++) s[nj][c] = 0.f;

        // S (log2-domain) = Q * K^T
        #pragma unroll
        for (int ks = 0; ks < 4; ks++) {
            #pragma unroll
            for (int njp = 0; njp < 4; njp++) {
                int krow = njp * 16 + (lane >> 4) * 8 + (lane & 7);
                uint32_t off = swo(krow, ks * 16 + ((lane >> 3) & 1) * 8);
                uint32_t kbh[4];
                ldmat4(kbh, kbb + off);
                mma16816(s[2 * njp],     qh[ks], kbh[0], kbh[1]);
                mma16816(s[2 * njp + 1], qh[ks], kbh[2], kbh[3]);
            }
        }

        // causal mask (near-diagonal tiles only)
        if (kt * 64 + 63 > q0 + 16 * w) {
            const int rowA = q0 + 16 * w + (lane >> 2);
            #pragma unroll
            for (int nj = 0; nj < 8; nj++)
                #pragma unroll
                for (int c = 0; c < 4; c++) {
                    int col = kt * 64 + nj * 8 + (lane & 3) * 2 + (c & 1);
                    if (col > rowA + (c >> 1) * 8) s[nj][c] = -1e30f;
                }
        }

        float mxA = -1e30f, mxB = -1e30f;
        #pragma unroll
        for (int nj = 0; nj < 8; nj++) {
            mxA = fmaxf(mxA, fmaxf(s[nj][0], s[nj][1]));
            mxB = fmaxf(mxB, fmaxf(s[nj][2], s[nj][3]));
        }
        #pragma unroll
        for (int off = 1; off < 4; off <<= 1) {
            mxA = fmaxf(mxA, __shfl_xor_sync(0xffffffffu, mxA, off));
            mxB = fmaxf(mxB, __shfl_xor_sync(0xffffffffu, mxB, off));
        }
        float mA = fmaxf(m[0], mxA), mB = fmaxf(m[1], mxB);
        float scA = fexp2(m[0] - mA), scB = fexp2(m[1] - mB);
        m[0] = mA; m[1] = mB;
        float sA = 0.f, sB = 0.f;
        #pragma unroll
        for (int nj = 0; nj < 8; nj++) {
            s[nj][0] = fexp2(s[nj][0] - mA); s[nj][1] = fexp2(s[nj][1] - mA);
            s[nj][2] = fexp2(s[nj][2] - mB); s[nj][3] = fexp2(s[nj][3] - mB);
            sA += s[nj][0] + s[nj][1];
            sB += s[nj][2] + s[nj][3];
        }
        #pragma unroll
        for (int off = 1; off < 4; off <<= 1) {
            sA += __shfl_xor_sync(0xffffffffu, sA, off);
            sB += __shfl_xor_sync(0xffffffffu, sB, off);
        }
        l[0] = l[0] * scA + sA;
        l[1] = l[1] * scB + sB;
        #pragma unroll
        for (int nj = 0; nj < 8; nj++) {
            o[nj][0] *= scA; o[nj][1] *= scA; o[nj][2] *= scB; o[nj][3] *= scB;
        }

        // O += P * V
        const uint32_t vbb = kbb + 8192;
        #pragma unroll
        for (int kk = 0; kk < 4; kk++) {
            uint32_t pah[4];
            CVTH2(pah[0], s[2 * kk][1],     s[2 * kk][0]);
            CVTH2(pah[1], s[2 * kk][3],     s[2 * kk][2]);
            CVTH2(pah[2], s[2 * kk + 1][1], s[2 * kk + 1][0]);
            CVTH2(pah[3], s[2 * kk + 1][3], s[2 * kk + 1][2]);
            int vrow = kk * 16 + (lane & 7) + ((lane >> 3) & 1) * 8;
            #pragma unroll
            for (int ep = 0; ep < 4; ep++) {
                uint32_t off = swo(vrow, ep * 16 + (lane >> 4) * 8);
                uint32_t vbh[4];
                ldmat4t(vbh, vbb + off);
                mma16816(o[2 * ep],     pah, vbh[0], vbh[1]);
                mma16816(o[2 * ep + 1], pah, vbh[2], vbh[3]);
            }
        }
    }

    const float invA = 1.f / l[0], invB = 1.f / l[1];
    const size_t base = (tq0 + 16 * w + (lane >> 2)) * Dm + h * 64;
    #pragma unroll
    for (int nj = 0; nj < 8; nj++) {
        const int col = nj * 8 + (lane & 3) * 2;
        uint32_t p0, p1;
        CVTH2(p0, o[nj][1] * invA, o[nj][0] * invA);
        CVTH2(p1, o[nj][3] * invB, o[nj][2] * invB);
        *(uint32_t*)(g_zh + base + col)          = p0;
        *(uint32_t*)(g_zh + base + 8 * Dm + col) = p1;
    }
}

// ---------------------------------------------------------------------------
extern "C" void kernel_launch(void* const* d_in, const int* in_sizes, int n_in,
                              void* d_out, int out_size)
{
    const float* x  = (const float*)d_in[0];
    const float* wq = (const float*)d_in[1];
    const float* bq = (const float*)d_in[2];
    const float* wk = (const float*)d_in[3];
    const float* bk = (const float*)d_in[4];
    const float* wv = (const float*)d_in[5];
    const float* bv = (const float*)d_in[6];
    const float* wo = (const float*)d_in[7];
    const float* bo = (const float*)d_in[8];
    float* out = (float*)d_out;

    cudaFuncSetAttribute(hmma_gemm, cudaFuncAttributeMaxDynamicSharedMemorySize, GEMM_SMEM);
    cudaFuncSetAttribute(fattn,     cudaFuncAttributeMaxDynamicSharedMemorySize, ATT_SMEM);

    void* p;
    cudaGetSymbolAddress(&p, g_xh); __half* xh = (__half*)p;
    cudaGetSymbolAddress(&p, g_zh); __half* zh = (__half*)p;
    cudaGetSymbolAddress(&p, g_wh); __half* wh = (__half*)p;
    cudaGetSymbolAddress(&p, g_oh); __half* oh = (__half*)p;

    conv_h<<<(Tt * Dm / 4 + 255) / 256, 256>>>(x, xh, Tt * Dm / 4);
    conv_wqkv<<<(3 * Dm * Dm + 255) / 256, 256>>>(wq, wk, wv);
    conv_wo<<<(Dm * Dm + 255) / 256, 256>>>(wo);

    hmma_gemm<<<dim3(Tt / 128, 24), 128, GEMM_SMEM>>>(
        xh, wh, bq, bk, bv, nullptr, 1);

    fattn<<<dim3(Sq / 128, Hh, Bsz), 256, ATT_SMEM>>>();

    hmma_gemm<<<dim3(Tt / 128, 8), 128, GEMM_SMEM>>>(
        zh, oh, bo, bo, bo, out, 0);
}